// round 1
// baseline (speedup 1.0000x reference)
#include <cuda_runtime.h>
#include <stdint.h>

#define NPIX 65536
#define NIMG 4
#define NPAIR (NPIX - 1)

// ---------------- device scratch (no allocations allowed) ----------------
__device__ uint32_t g_keyA[NIMG * NPIX];
__device__ uint32_t g_keyB[NIMG * NPIX];
__device__ uint32_t g_payA[NIMG * NPIX];
__device__ uint32_t g_payB[NIMG * NPIX];
__device__ float    g_fval[NIMG * NPIX];
__device__ uint16_t g_rank16[NIMG * NPIX];
__device__ float    g_sortedf[NIMG * NPIX];
__device__ unsigned long long g_nbrs[NIMG * NPIX];
__device__ unsigned long long g_pairs[NIMG * NPAIR];
__device__ float    g_loss[NIMG];

// ---------------- 1) f = 1 - prob*roi, keys = float bits --------------------
__global__ void k_init(const float* __restrict__ prob, const float* __restrict__ roi) {
    int i = blockIdx.x * blockDim.x + threadIdx.x;
    if (i < NIMG * NPIX) {
        float f = 1.0f - prob[i] * roi[i];     // f in (0,1], positive -> bits monotone
        g_fval[i] = f;
        g_keyA[i] = __float_as_uint(f);
        g_payA[i] = (uint32_t)(i & (NPIX - 1));
    }
}

// ---------------- 2) per-image stable LSD radix sort (8 x 4-bit) ------------
// 1 block per image, 1024 threads, thread t owns elements [t*64, t*64+64).
// Stability: scan order (digit-major, thread-minor) matches element order
// (thread-chunk, in-chunk), so ties keep original index order -> rank order
// is exactly the reference's (fvc, idx) lexicographic order.
__global__ void __launch_bounds__(1024, 1) k_radix() {
    extern __shared__ uint32_t hist[];          // 16 * 1024 u32 = 64 KB
    __shared__ uint32_t warpsum[32];
    const int img  = blockIdx.x;
    const int tid  = threadIdx.x;
    const int lane = tid & 31;
    const int wid  = tid >> 5;
    const uint32_t off = (uint32_t)img * NPIX;

    for (int pass = 0; pass < 8; pass++) {
        uint32_t *src, *dst, *ps, *pd;
        if (pass & 1) { src = g_keyB; dst = g_keyA; ps = g_payB; pd = g_payA; }
        else          { src = g_keyA; dst = g_keyB; ps = g_payA; pd = g_payB; }
        src += off; dst += off; ps += off; pd += off;
        const int shift = pass * 4;

        #pragma unroll
        for (int i = 0; i < 16; i++) hist[i * 1024 + tid] = 0;
        __syncthreads();

        const int base = tid * 64;
        for (int j = 0; j < 64; j++) {
            uint32_t d = (src[base + j] >> shift) & 15u;
            hist[(d << 10) + tid]++;
        }
        __syncthreads();

        // exclusive scan of 16384 counters in flattened (digit, thread) order
        const int sb = tid * 16;
        uint32_t sum = 0;
        #pragma unroll
        for (int i = 0; i < 16; i++) sum += hist[sb + i];
        uint32_t v = sum;
        #pragma unroll
        for (int o = 1; o < 32; o <<= 1) {
            uint32_t n = __shfl_up_sync(0xFFFFFFFFu, v, o);
            if (lane >= o) v += n;
        }
        if (lane == 31) warpsum[wid] = v;
        __syncthreads();
        if (wid == 0) {
            uint32_t w  = warpsum[lane];
            uint32_t wv = w;
            #pragma unroll
            for (int o = 1; o < 32; o <<= 1) {
                uint32_t n = __shfl_up_sync(0xFFFFFFFFu, wv, o);
                if (lane >= o) wv += n;
            }
            warpsum[lane] = wv - w;              // exclusive warp offsets
        }
        __syncthreads();
        uint32_t run = (v - sum) + warpsum[wid]; // exclusive prefix for this thread
        #pragma unroll
        for (int i = 0; i < 16; i++) { uint32_t t = hist[sb + i]; hist[sb + i] = run; run += t; }
        __syncthreads();

        for (int j = 0; j < 64; j++) {
            uint32_t k = src[base + j];
            uint32_t d = (k >> shift) & 15u;
            uint32_t pos = hist[(d << 10) + tid]++;
            dst[pos] = k;
            pd[pos]  = ps[base + j];
        }
        __syncthreads();
    }
}

// ---------------- 3) rank (inverse perm) + f gathered in rank order ---------
__global__ void k_rank() {
    int i = blockIdx.x * blockDim.x + threadIdx.x;
    if (i < NIMG * NPIX) {
        int img = i >> 16;
        int r   = i & (NPIX - 1);
        uint32_t pix = g_payA[i];                // pixel with rank r
        g_rank16[(img << 16) + pix] = (uint16_t)r;
        g_sortedf[i] = g_fval[(img << 16) + pix];
    }
}

// ---------------- 4) packed neighbor ranks, indexed by rank -----------------
// 0xFFFF sentinel for out-of-grid is safe: skip condition in UF is (q < r),
// and a genuine rank 65535 neighbor is also always >= r, so it is (correctly)
// handled when rank 65535 itself is processed.
__global__ void k_nbr() {
    int i = blockIdx.x * blockDim.x + threadIdx.x;
    if (i < NIMG * NPIX) {
        int img = i >> 16;
        uint32_t pix = (uint32_t)(i & (NPIX - 1));
        const uint16_t* rk = g_rank16 + ((size_t)img << 16);
        uint32_t r = rk[pix];
        int y = pix >> 8, x = pix & 255;
        unsigned long long n0 = (y > 0)   ? (unsigned long long)rk[pix - 256] : 0xFFFFull;
        unsigned long long n1 = (y < 255) ? (unsigned long long)rk[pix + 256] : 0xFFFFull;
        unsigned long long n2 = (x > 0)   ? (unsigned long long)rk[pix - 1]   : 0xFFFFull;
        unsigned long long n3 = (x < 255) ? (unsigned long long)rk[pix + 1]   : 0xFFFFull;
        g_nbrs[((size_t)img << 16) + r] = n0 | (n1 << 16) | (n2 << 32) | (n3 << 48);
    }
}

// ---------------- 5) serial Kruskal / union-find in shared memory -----------
// Rank relabeling: elder rule == integer min of root ids. Parent fits u16.
// Merge records (death_bits, dying_root) streamed to global; birth gathers
// deferred to the parallel top-k kernel (avoids 65535 serialized L2 hits).
__global__ void __launch_bounds__(1024, 1) k_uf() {
    extern __shared__ uint16_t par[];            // 65536 * u16 = 128 KB
    const int img = blockIdx.x;
    const int tid = threadIdx.x;
    for (int i = tid; i < NPIX; i += 1024) par[i] = (uint16_t)i;
    __syncthreads();
    if (tid != 0) return;

    const unsigned long long* __restrict__ nb = g_nbrs + ((size_t)img << 16);
    const float* __restrict__ sf = g_sortedf + ((size_t)img << 16);
    unsigned long long* __restrict__ pr = g_pairs + (size_t)img * NPAIR;
    uint32_t cnt = 0;

    for (uint32_t r = 0; r < NPIX; r++) {
        unsigned long long w = nb[r];
        uint32_t cur = r;                        // root of r's current component
        float death = sf[r];                     // edge weight = f at max-rank endpoint
        #pragma unroll
        for (int k = 0; k < 4; k++) {
            uint32_t q = (uint32_t)(w >> (k * 16)) & 0xFFFFu;
            if (q < r) {
                // find with path halving
                uint32_t x = q;
                uint32_t p = par[x];
                while (p != x) {
                    uint32_t g = par[p];
                    par[x] = (uint16_t)g;
                    x = g;
                    p = par[x];
                }
                if (x != cur) {
                    uint32_t die  = x > cur ? x : cur;  // younger = larger rank root
                    uint32_t keep = x > cur ? cur : x;
                    par[die] = (uint16_t)keep;
                    cur = keep;
                    pr[cnt++] = ((unsigned long long)__float_as_uint(death) << 32)
                              | (unsigned long long)die;
                }
            }
        }
    }
    // connected grid => cnt == NPAIR always
}

// ---------------- 6) parallel top-5 lifetimes + per-image loss --------------
__device__ __forceinline__ void top5_ins(float& t0, float& t1, float& t2,
                                         float& t3, float& t4, float life) {
    if (life <= t4) return;
    if (life > t0)      { t4 = t3; t3 = t2; t2 = t1; t1 = t0; t0 = life; }
    else if (life > t1) { t4 = t3; t3 = t2; t2 = t1; t1 = life; }
    else if (life > t2) { t4 = t3; t3 = t2; t2 = life; }
    else if (life > t3) { t4 = t3; t3 = life; }
    else                  t4 = life;
}

__global__ void __launch_bounds__(1024, 1) k_top() {
    __shared__ float cand[1024 * 5];
    const int img = blockIdx.x;
    const int tid = threadIdx.x;
    const unsigned long long* __restrict__ pr = g_pairs + (size_t)img * NPAIR;
    const float* __restrict__ sf = g_sortedf + ((size_t)img << 16);

    float t0 = -1e30f, t1 = -1e30f, t2 = -1e30f, t3 = -1e30f, t4 = -1e30f;
    for (int i = tid; i < NPAIR; i += 1024) {
        unsigned long long w = pr[i];
        float death = __uint_as_float((uint32_t)(w >> 32));
        uint32_t die = (uint32_t)w & 0xFFFFu;
        float life = death - sf[die];            // birth = f at dying root (comp. argmin)
        top5_ins(t0, t1, t2, t3, t4, life);
    }
    cand[tid * 5 + 0] = t0; cand[tid * 5 + 1] = t1; cand[tid * 5 + 2] = t2;
    cand[tid * 5 + 3] = t3; cand[tid * 5 + 4] = t4;
    __syncthreads();
    if (tid == 0) {
        float s0 = -1e30f, s1 = -1e30f, s2 = -1e30f, s3 = -1e30f, s4 = -1e30f;
        for (int i = 0; i < 1024 * 5; i++) top5_ins(s0, s1, s2, s3, s4, cand[i]);
        float d0 = s0 - 0.5f, d1 = s1 - 0.5f, d2 = s2 - 0.5f, d3 = s3 - 0.5f, d4 = s4 - 0.5f;
        g_loss[img] = (d0 * d0 + d1 * d1 + d2 * d2 + d3 * d3 + d4 * d4) * 0.2f;
    }
}

__global__ void k_final(float* out) {
    out[0] = (g_loss[0] + g_loss[1] + g_loss[2] + g_loss[3]) * 25.0f; // mean/4 * 100
}

// ---------------- launch -----------------------------------------------------
extern "C" void kernel_launch(void* const* d_in, const int* in_sizes, int n_in,
                              void* d_out, int out_size) {
    (void)in_sizes; (void)n_in; (void)out_size;
    const float* prob = (const float*)d_in[0];
    const float* roi  = (const float*)d_in[1];
    float* out = (float*)d_out;

    cudaFuncSetAttribute(k_radix, cudaFuncAttributeMaxDynamicSharedMemorySize, 16 * 1024 * 4);
    cudaFuncSetAttribute(k_uf,    cudaFuncAttributeMaxDynamicSharedMemorySize, NPIX * 2);

    const int nTot = NIMG * NPIX;
    k_init<<<(nTot + 255) / 256, 256>>>(prob, roi);
    k_radix<<<NIMG, 1024, 16 * 1024 * 4>>>();
    k_rank<<<(nTot + 255) / 256, 256>>>();
    k_nbr<<<(nTot + 255) / 256, 256>>>();
    k_uf<<<NIMG, 1024, NPIX * 2>>>();
    k_top<<<NIMG, 1024>>>();
    k_final<<<1, 1>>>(out);
}

// round 2
// speedup vs baseline: 1.3428x; 1.3428x over previous
#include <cuda_runtime.h>
#include <stdint.h>

#define NPIX 65536
#define NIMG 4
#define EMAX 131072            // >= 2*256*255 edges per image
#define PMAX 32768             // >= max #local minima per image

// ---------------- device scratch (no allocations allowed) ----------------
__device__ uint32_t g_keyA[NIMG * NPIX];
__device__ uint32_t g_keyB[NIMG * NPIX];
__device__ uint32_t g_payA[NIMG * NPIX];
__device__ uint32_t g_payB[NIMG * NPIX];
__device__ float    g_fval[NIMG * NPIX];
__device__ uint16_t g_rank16[NIMG * NPIX];
__device__ float    g_sortedf[NIMG * NPIX];
__device__ unsigned long long g_nbrs[NIMG * NPIX];
__device__ uint16_t g_basin[NIMG * NPIX];
__device__ uint32_t g_erecA[NIMG * EMAX];
__device__ uint32_t g_erecB[NIMG * EMAX];
__device__ int      g_ecnt[NIMG];
__device__ uint32_t g_pairs[NIMG * PMAX];
__device__ int      g_pcnt[NIMG];
__device__ float    g_loss[NIMG];

// ---------------- 1) f = 1 - prob*roi, keys = float bits --------------------
__global__ void k_init(const float* __restrict__ prob, const float* __restrict__ roi) {
    int i = blockIdx.x * blockDim.x + threadIdx.x;
    if (i < NIMG) g_ecnt[i] = 0;
    if (i < NIMG * NPIX) {
        float f = 1.0f - prob[i] * roi[i];     // f in (0,1], positive -> bits monotone
        g_fval[i] = f;
        g_keyA[i] = __float_as_uint(f);
        g_payA[i] = (uint32_t)(i & (NPIX - 1));
    }
}

// ---------------- 2) per-image stable LSD radix sort (8 x 4-bit) ------------
__global__ void __launch_bounds__(1024, 1) k_radix() {
    extern __shared__ uint32_t hist[];          // 16 * 1024 u32 = 64 KB
    __shared__ uint32_t warpsum[32];
    const int img  = blockIdx.x;
    const int tid  = threadIdx.x;
    const int lane = tid & 31;
    const int wid  = tid >> 5;
    const uint32_t off = (uint32_t)img * NPIX;

    for (int pass = 0; pass < 8; pass++) {
        uint32_t *src, *dst, *ps, *pd;
        if (pass & 1) { src = g_keyB; dst = g_keyA; ps = g_payB; pd = g_payA; }
        else          { src = g_keyA; dst = g_keyB; ps = g_payA; pd = g_payB; }
        src += off; dst += off; ps += off; pd += off;
        const int shift = pass * 4;

        #pragma unroll
        for (int i = 0; i < 16; i++) hist[i * 1024 + tid] = 0;
        __syncthreads();

        const int base = tid * 64;
        for (int j = 0; j < 64; j++) {
            uint32_t d = (src[base + j] >> shift) & 15u;
            hist[(d << 10) + tid]++;
        }
        __syncthreads();

        const int sb = tid * 16;
        uint32_t sum = 0;
        #pragma unroll
        for (int i = 0; i < 16; i++) sum += hist[sb + i];
        uint32_t v = sum;
        #pragma unroll
        for (int o = 1; o < 32; o <<= 1) {
            uint32_t n = __shfl_up_sync(0xFFFFFFFFu, v, o);
            if (lane >= o) v += n;
        }
        if (lane == 31) warpsum[wid] = v;
        __syncthreads();
        if (wid == 0) {
            uint32_t w  = warpsum[lane];
            uint32_t wv = w;
            #pragma unroll
            for (int o = 1; o < 32; o <<= 1) {
                uint32_t n = __shfl_up_sync(0xFFFFFFFFu, wv, o);
                if (lane >= o) wv += n;
            }
            warpsum[lane] = wv - w;
        }
        __syncthreads();
        uint32_t run = (v - sum) + warpsum[wid];
        #pragma unroll
        for (int i = 0; i < 16; i++) { uint32_t t = hist[sb + i]; hist[sb + i] = run; run += t; }
        __syncthreads();

        for (int j = 0; j < 64; j++) {
            uint32_t k = src[base + j];
            uint32_t d = (k >> shift) & 15u;
            uint32_t pos = hist[(d << 10) + tid]++;
            dst[pos] = k;
            pd[pos]  = ps[base + j];
        }
        __syncthreads();
    }
}

// ---------------- 3) rank (inverse perm) + f gathered in rank order ---------
__global__ void k_rank() {
    int i = blockIdx.x * blockDim.x + threadIdx.x;
    if (i < NIMG * NPIX) {
        int img = i >> 16;
        uint32_t pix = g_payA[i];
        g_rank16[(img << 16) + pix] = (uint16_t)(i & (NPIX - 1));
        g_sortedf[i] = g_fval[(img << 16) + pix];
    }
}

// ---------------- 4) packed neighbor ranks, indexed by rank -----------------
__global__ void k_nbr() {
    int i = blockIdx.x * blockDim.x + threadIdx.x;
    if (i < NIMG * NPIX) {
        int img = i >> 16;
        uint32_t pix = (uint32_t)(i & (NPIX - 1));
        const uint16_t* rk = g_rank16 + ((size_t)img << 16);
        uint32_t r = rk[pix];
        int y = pix >> 8, x = pix & 255;
        unsigned long long n0 = (y > 0)   ? (unsigned long long)rk[pix - 256] : 0xFFFFull;
        unsigned long long n1 = (y < 255) ? (unsigned long long)rk[pix + 256] : 0xFFFFull;
        unsigned long long n2 = (x > 0)   ? (unsigned long long)rk[pix - 1]   : 0xFFFFull;
        unsigned long long n3 = (x < 255) ? (unsigned long long)rk[pix + 1]   : 0xFFFFull;
        g_nbrs[((size_t)img << 16) + r] = n0 | (n1 << 16) | (n2 << 32) | (n3 << 48);
    }
}

// ---------------- 5) basins: steepest-descent forest + pointer doubling -----
// b[r] = min-rank neighbor if lower else self; 16 in-place jumping rounds
// guarantee convergence for any chain length <= 65536.
__global__ void __launch_bounds__(1024, 1) k_basin() {
    extern __shared__ uint16_t bs[];             // 65536 * u16 = 128 KB
    const int img = blockIdx.x;
    const int tid = threadIdx.x;
    const unsigned long long* __restrict__ nb = g_nbrs + ((size_t)img << 16);

    for (int i = tid; i < NPIX; i += 1024) {
        unsigned long long w = nb[i];
        uint32_t m0 = (uint32_t)(w & 0xFFFF), m1 = (uint32_t)((w >> 16) & 0xFFFF);
        uint32_t m2 = (uint32_t)((w >> 32) & 0xFFFF), m3 = (uint32_t)(w >> 48);
        uint32_t m = min(min(m0, m1), min(m2, m3));
        bs[i] = (uint16_t)((m < (uint32_t)i) ? m : (uint32_t)i);
    }
    __syncthreads();
    for (int round = 0; round < 16; round++) {
        for (int i = tid; i < NPIX; i += 1024) {
            uint32_t p = bs[i];
            bs[i] = bs[p];
        }
        __syncthreads();
    }
    uint16_t* out = g_basin + ((size_t)img << 16);
    for (int i = tid; i < NPIX; i += 1024) out[i] = bs[i];
}

// ---------------- 6) emit crossing edges (different basins), key = max rank -
__global__ void k_edges() {
    int i = blockIdx.x * blockDim.x + threadIdx.x;
    if (i >= NIMG * NPIX) return;
    int img = i >> 16;
    uint32_t r = (uint32_t)(i & (NPIX - 1));
    const uint16_t* bs = g_basin + ((size_t)img << 16);
    unsigned long long w = g_nbrs[i];
    uint32_t br = bs[r];

    uint32_t recs[3];
    int cnt = 0;
    #pragma unroll
    for (int k = 0; k < 4; k++) {
        uint32_t q = (uint32_t)(w >> (k * 16)) & 0xFFFFu;
        if (q < r && bs[q] != br) recs[cnt++] = (r << 16) | q;
    }
    // warp-aggregated append
    int lane = threadIdx.x & 31;
    int pre = cnt;
    #pragma unroll
    for (int o = 1; o < 32; o <<= 1) {
        int n = __shfl_up_sync(0xFFFFFFFFu, pre, o);
        if (lane >= o) pre += n;
    }
    int total = __shfl_sync(0xFFFFFFFFu, pre, 31);
    int excl = pre - cnt;
    int base = 0;
    if (lane == 31 && total > 0) base = atomicAdd(&g_ecnt[img], total);
    base = __shfl_sync(0xFFFFFFFFu, base, 31);
    uint32_t* er = g_erecA + (size_t)img * EMAX;
    for (int j = 0; j < cnt; j++) er[base + excl + j] = recs[j];
}

// ---------------- 7) per-image radix sort of edges by key bits [16,32) ------
__global__ void __launch_bounds__(1024, 1) k_sort() {
    extern __shared__ uint32_t hist[];          // 64 KB
    __shared__ uint32_t warpsum[32];
    const int img  = blockIdx.x;
    const int tid  = threadIdx.x;
    const int lane = tid & 31;
    const int wid  = tid >> 5;
    const int n = g_ecnt[img];
    const size_t off = (size_t)img * EMAX;

    for (int pass = 0; pass < 4; pass++) {
        const uint32_t* src = (pass & 1) ? g_erecB + off : g_erecA + off;
        uint32_t*       dst = (pass & 1) ? g_erecA + off : g_erecB + off;
        const int shift = 16 + pass * 4;

        #pragma unroll
        for (int i = 0; i < 16; i++) hist[i * 1024 + tid] = 0;
        __syncthreads();

        const int base = tid * 128;
        for (int j = 0; j < 128; j++) {
            int idx = base + j;
            if (idx < n) {
                uint32_t d = (src[idx] >> shift) & 15u;
                hist[(d << 10) + tid]++;
            }
        }
        __syncthreads();

        const int sb = tid * 16;
        uint32_t sum = 0;
        #pragma unroll
        for (int i = 0; i < 16; i++) sum += hist[sb + i];
        uint32_t v = sum;
        #pragma unroll
        for (int o = 1; o < 32; o <<= 1) {
            uint32_t t = __shfl_up_sync(0xFFFFFFFFu, v, o);
            if (lane >= o) v += t;
        }
        if (lane == 31) warpsum[wid] = v;
        __syncthreads();
        if (wid == 0) {
            uint32_t w  = warpsum[lane];
            uint32_t wv = w;
            #pragma unroll
            for (int o = 1; o < 32; o <<= 1) {
                uint32_t t = __shfl_up_sync(0xFFFFFFFFu, wv, o);
                if (lane >= o) wv += t;
            }
            warpsum[lane] = wv - w;
        }
        __syncthreads();
        uint32_t run = (v - sum) + warpsum[wid];
        #pragma unroll
        for (int i = 0; i < 16; i++) { uint32_t t = hist[sb + i]; hist[sb + i] = run; run += t; }
        __syncthreads();

        for (int j = 0; j < 128; j++) {
            int idx = base + j;
            if (idx < n) {
                uint32_t k = src[idx];
                uint32_t d = (k >> shift) & 15u;
                dst[hist[(d << 10) + tid]++] = k;
            }
        }
        __syncthreads();
    }
}

// ---------------- 8) serial Kruskal on crossing edges, par preseeded --------
__device__ __forceinline__ uint32_t uf_find(uint16_t* par, uint32_t x) {
    uint32_t p = par[x];
    while (p != x) {                 // path halving
        uint32_t g = par[p];
        par[x] = (uint16_t)g;
        x = g;
        p = par[x];
    }
    return x;
}

__global__ void __launch_bounds__(1024, 1) k_uf() {
    extern __shared__ uint16_t par[];            // 128 KB
    const int img = blockIdx.x;
    const int tid = threadIdx.x;
    // preseed with basin roots (coalesced u32 copies)
    const uint32_t* bsrc = (const uint32_t*)(g_basin + ((size_t)img << 16));
    uint32_t* pdst = (uint32_t*)par;
    for (int i = tid; i < NPIX / 2; i += 1024) pdst[i] = bsrc[i];
    __syncthreads();
    if (tid != 0) return;

    const uint32_t* __restrict__ rec = g_erecA + (size_t)img * EMAX;  // sorted (4 passes)
    uint32_t* __restrict__ out = g_pairs + (size_t)img * PMAX;
    const int m = g_ecnt[img];

    uint32_t pcnt = 0;
    uint32_t last_r = 0xFFFFFFFFu, root_r = 0;
    for (int i = 0; i < m; i++) {
        uint32_t e = rec[i];
        uint32_t r = e >> 16;
        uint32_t q = e & 0xFFFFu;
        if (r != last_r) { last_r = r; root_r = uf_find(par, r); }
        uint32_t rq = uf_find(par, q);
        if (rq != root_r) {
            uint32_t die  = rq > root_r ? rq : root_r;
            uint32_t keep = rq > root_r ? root_r : rq;
            par[die] = (uint16_t)keep;
            root_r = keep;
            out[pcnt++] = (r << 16) | die;       // death rank | birth(root) rank
        }
    }
    g_pcnt[img] = (int)pcnt;
}

// ---------------- 9) parallel top-5 lifetimes + per-image loss --------------
__device__ __forceinline__ void top5_ins(float& t0, float& t1, float& t2,
                                         float& t3, float& t4, float life) {
    if (life <= t4) return;
    if (life > t0)      { t4 = t3; t3 = t2; t2 = t1; t1 = t0; t0 = life; }
    else if (life > t1) { t4 = t3; t3 = t2; t2 = t1; t1 = life; }
    else if (life > t2) { t4 = t3; t3 = t2; t2 = life; }
    else if (life > t3) { t4 = t3; t3 = life; }
    else                  t4 = life;
}

__global__ void __launch_bounds__(1024, 1) k_top() {
    __shared__ float cand[1024 * 5];
    const int img = blockIdx.x;
    const int tid = threadIdx.x;
    const uint32_t* __restrict__ pr = g_pairs + (size_t)img * PMAX;
    const float* __restrict__ sf = g_sortedf + ((size_t)img << 16);
    const int m = g_pcnt[img];

    float t0 = -1e30f, t1 = -1e30f, t2 = -1e30f, t3 = -1e30f, t4 = -1e30f;
    for (int i = tid; i < m; i += 1024) {
        uint32_t e = pr[i];
        float life = sf[e >> 16] - sf[e & 0xFFFFu];
        top5_ins(t0, t1, t2, t3, t4, life);
    }
    cand[tid * 5 + 0] = t0; cand[tid * 5 + 1] = t1; cand[tid * 5 + 2] = t2;
    cand[tid * 5 + 3] = t3; cand[tid * 5 + 4] = t4;
    __syncthreads();
    if (tid == 0) {
        float s0 = -1e30f, s1 = -1e30f, s2 = -1e30f, s3 = -1e30f, s4 = -1e30f;
        for (int i = 0; i < 1024 * 5; i++) top5_ins(s0, s1, s2, s3, s4, cand[i]);
        // if fewer than 5 positive pairs, reference would pick 0-lifetime pairs
        if (s0 < -1e29f) s0 = 0.0f;
        if (s1 < -1e29f) s1 = 0.0f;
        if (s2 < -1e29f) s2 = 0.0f;
        if (s3 < -1e29f) s3 = 0.0f;
        if (s4 < -1e29f) s4 = 0.0f;
        float d0 = s0 - 0.5f, d1 = s1 - 0.5f, d2 = s2 - 0.5f, d3 = s3 - 0.5f, d4 = s4 - 0.5f;
        g_loss[img] = (d0 * d0 + d1 * d1 + d2 * d2 + d3 * d3 + d4 * d4) * 0.2f;
    }
}

__global__ void k_final(float* out) {
    out[0] = (g_loss[0] + g_loss[1] + g_loss[2] + g_loss[3]) * 25.0f; // mean/4 * 100
}

// ---------------- launch -----------------------------------------------------
extern "C" void kernel_launch(void* const* d_in, const int* in_sizes, int n_in,
                              void* d_out, int out_size) {
    (void)in_sizes; (void)n_in; (void)out_size;
    const float* prob = (const float*)d_in[0];
    const float* roi  = (const float*)d_in[1];
    float* out = (float*)d_out;

    cudaFuncSetAttribute(k_radix, cudaFuncAttributeMaxDynamicSharedMemorySize, 64 * 1024);
    cudaFuncSetAttribute(k_sort,  cudaFuncAttributeMaxDynamicSharedMemorySize, 64 * 1024);
    cudaFuncSetAttribute(k_basin, cudaFuncAttributeMaxDynamicSharedMemorySize, NPIX * 2);
    cudaFuncSetAttribute(k_uf,    cudaFuncAttributeMaxDynamicSharedMemorySize, NPIX * 2);

    const int nTot = NIMG * NPIX;
    k_init<<<(nTot + 255) / 256, 256>>>(prob, roi);
    k_radix<<<NIMG, 1024, 64 * 1024>>>();
    k_rank<<<(nTot + 255) / 256, 256>>>();
    k_nbr<<<(nTot + 255) / 256, 256>>>();
    k_basin<<<NIMG, 1024, NPIX * 2>>>();
    k_edges<<<(nTot + 255) / 256, 256>>>();
    k_sort<<<NIMG, 1024, 64 * 1024>>>();
    k_uf<<<NIMG, 1024, NPIX * 2>>>();
    k_top<<<NIMG, 1024>>>();
    k_final<<<1, 1>>>(out);
}

// round 3
// speedup vs baseline: 4.6032x; 3.4281x over previous
#include <cuda_runtime.h>
#include <stdint.h>

#define NPIX 65536
#define NIMG 4
#define EMAX 131072            // >= 2*256*255 edges per image
#define PMAX 32768             // max #local minima (independent set bound)

// ---------------- device scratch (no allocations allowed) ----------------
__device__ uint32_t g_keyA[NIMG * NPIX];
__device__ uint32_t g_keyB[NIMG * NPIX];
__device__ uint32_t g_payA[NIMG * NPIX];
__device__ uint32_t g_payB[NIMG * NPIX];
__device__ float    g_fval[NIMG * NPIX];
__device__ uint16_t g_rank16[NIMG * NPIX];
__device__ float    g_sortedf[NIMG * NPIX];
__device__ unsigned long long g_nbrs[NIMG * NPIX];
__device__ uint16_t g_basin[NIMG * NPIX];
__device__ uint16_t g_dense[NIMG * NPIX];
__device__ uint16_t g_minrank[NIMG * PMAX];
__device__ int      g_nmin[NIMG];
__device__ unsigned long long g_edges[NIMG * EMAX];
__device__ int      g_ecnt[NIMG];
__device__ unsigned long long g_mstA[NIMG * PMAX];
__device__ unsigned long long g_mstB[NIMG * PMAX];
__device__ int      g_mcnt[NIMG];
__device__ uint32_t g_pairs[NIMG * PMAX];
__device__ int      g_pcnt[NIMG];
__device__ float    g_loss[NIMG];

// ---------------- 1) f = 1 - prob*roi, keys = float bits --------------------
__global__ void k_init(const float* __restrict__ prob, const float* __restrict__ roi) {
    int i = blockIdx.x * blockDim.x + threadIdx.x;
    if (i < NIMG) { g_ecnt[i] = 0; g_mcnt[i] = 0; }
    if (i < NIMG * NPIX) {
        float f = 1.0f - prob[i] * roi[i];
        g_fval[i] = f;
        g_keyA[i] = __float_as_uint(f);   // f>0 -> bit order == float order
        g_payA[i] = (uint32_t)(i & (NPIX - 1));
    }
}

// ---------------- 2) per-image stable LSD radix sort (8 x 4-bit) ------------
__global__ void __launch_bounds__(1024, 1) k_radix() {
    extern __shared__ uint32_t hist[];          // 64 KB
    __shared__ uint32_t warpsum[32];
    const int img  = blockIdx.x;
    const int tid  = threadIdx.x;
    const int lane = tid & 31;
    const int wid  = tid >> 5;
    const uint32_t off = (uint32_t)img * NPIX;

    for (int pass = 0; pass < 8; pass++) {
        uint32_t *src, *dst, *ps, *pd;
        if (pass & 1) { src = g_keyB; dst = g_keyA; ps = g_payB; pd = g_payA; }
        else          { src = g_keyA; dst = g_keyB; ps = g_payA; pd = g_payB; }
        src += off; dst += off; ps += off; pd += off;
        const int shift = pass * 4;

        #pragma unroll
        for (int i = 0; i < 16; i++) hist[i * 1024 + tid] = 0;
        __syncthreads();

        const int base = tid * 64;
        for (int j = 0; j < 64; j++) {
            uint32_t d = (src[base + j] >> shift) & 15u;
            hist[(d << 10) + tid]++;
        }
        __syncthreads();

        const int sb = tid * 16;
        uint32_t sum = 0;
        #pragma unroll
        for (int i = 0; i < 16; i++) sum += hist[sb + i];
        uint32_t v = sum;
        #pragma unroll
        for (int o = 1; o < 32; o <<= 1) {
            uint32_t n = __shfl_up_sync(0xFFFFFFFFu, v, o);
            if (lane >= o) v += n;
        }
        if (lane == 31) warpsum[wid] = v;
        __syncthreads();
        if (wid == 0) {
            uint32_t w  = warpsum[lane];
            uint32_t wv = w;
            #pragma unroll
            for (int o = 1; o < 32; o <<= 1) {
                uint32_t n = __shfl_up_sync(0xFFFFFFFFu, wv, o);
                if (lane >= o) wv += n;
            }
            warpsum[lane] = wv - w;
        }
        __syncthreads();
        uint32_t run = (v - sum) + warpsum[wid];
        #pragma unroll
        for (int i = 0; i < 16; i++) { uint32_t t = hist[sb + i]; hist[sb + i] = run; run += t; }
        __syncthreads();

        for (int j = 0; j < 64; j++) {
            uint32_t k = src[base + j];
            uint32_t d = (k >> shift) & 15u;
            uint32_t pos = hist[(d << 10) + tid]++;
            dst[pos] = k;
            pd[pos]  = ps[base + j];
        }
        __syncthreads();
    }
}

// ---------------- 3) rank (inverse perm) + f gathered in rank order ---------
__global__ void k_rank() {
    int i = blockIdx.x * blockDim.x + threadIdx.x;
    if (i < NIMG * NPIX) {
        int img = i >> 16;
        uint32_t pix = g_payA[i];
        g_rank16[(img << 16) + pix] = (uint16_t)(i & (NPIX - 1));
        g_sortedf[i] = g_fval[(img << 16) + pix];
    }
}

// ---------------- 4) packed neighbor ranks, indexed by rank -----------------
__global__ void k_nbr() {
    int i = blockIdx.x * blockDim.x + threadIdx.x;
    if (i < NIMG * NPIX) {
        int img = i >> 16;
        uint32_t pix = (uint32_t)(i & (NPIX - 1));
        const uint16_t* rk = g_rank16 + ((size_t)img << 16);
        uint32_t r = rk[pix];
        int y = pix >> 8, x = pix & 255;
        unsigned long long n0 = (y > 0)   ? (unsigned long long)rk[pix - 256] : 0xFFFFull;
        unsigned long long n1 = (y < 255) ? (unsigned long long)rk[pix + 256] : 0xFFFFull;
        unsigned long long n2 = (x > 0)   ? (unsigned long long)rk[pix - 1]   : 0xFFFFull;
        unsigned long long n3 = (x < 255) ? (unsigned long long)rk[pix + 1]   : 0xFFFFull;
        g_nbrs[((size_t)img << 16) + r] = n0 | (n1 << 16) | (n2 << 32) | (n3 << 48);
    }
}

// ---------------- 5) basins: steepest-descent forest + pointer doubling -----
__global__ void __launch_bounds__(1024, 1) k_basin() {
    extern __shared__ uint16_t bs[];             // 128 KB
    const int img = blockIdx.x;
    const int tid = threadIdx.x;
    const unsigned long long* __restrict__ nb = g_nbrs + ((size_t)img << 16);

    for (int i = tid; i < NPIX; i += 1024) {
        unsigned long long w = nb[i];
        uint32_t m0 = (uint32_t)(w & 0xFFFF), m1 = (uint32_t)((w >> 16) & 0xFFFF);
        uint32_t m2 = (uint32_t)((w >> 32) & 0xFFFF), m3 = (uint32_t)(w >> 48);
        uint32_t m = min(min(m0, m1), min(m2, m3));
        bs[i] = (uint16_t)((m < (uint32_t)i) ? m : (uint32_t)i);
    }
    __syncthreads();
    for (int round = 0; round < 16; round++) {
        for (int i = tid; i < NPIX; i += 1024) {
            uint32_t p = bs[i];
            bs[i] = bs[p];
        }
        __syncthreads();
    }
    uint16_t* out = g_basin + ((size_t)img << 16);
    for (int i = tid; i < NPIX; i += 1024) out[i] = bs[i];
}

// ---------------- 6) dense basin ids (ascending rank => ascending birth) ----
__global__ void __launch_bounds__(1024, 1) k_dense() {
    __shared__ uint32_t warpsum[32];
    const int img = blockIdx.x, tid = threadIdx.x;
    const int lane = tid & 31, wid = tid >> 5;
    const uint16_t* bs = g_basin + ((size_t)img << 16);
    const int base = tid * 64;

    uint32_t cnt = 0;
    for (int j = 0; j < 64; j++) cnt += (bs[base + j] == (uint16_t)(base + j));
    uint32_t v = cnt;
    #pragma unroll
    for (int o = 1; o < 32; o <<= 1) {
        uint32_t n = __shfl_up_sync(0xFFFFFFFFu, v, o);
        if (lane >= o) v += n;
    }
    if (lane == 31) warpsum[wid] = v;
    __syncthreads();
    if (wid == 0) {
        uint32_t w  = warpsum[lane];
        uint32_t wv = w;
        #pragma unroll
        for (int o = 1; o < 32; o <<= 1) {
            uint32_t n = __shfl_up_sync(0xFFFFFFFFu, wv, o);
            if (lane >= o) wv += n;
        }
        warpsum[lane] = wv - w;
    }
    __syncthreads();
    uint32_t run = (v - cnt) + warpsum[wid];
    uint16_t* dn = g_dense   + ((size_t)img << 16);
    uint16_t* mr = g_minrank + (size_t)img * PMAX;
    for (int j = 0; j < 64; j++) {
        int i = base + j;
        if (bs[i] == (uint16_t)i) { dn[i] = (uint16_t)run; mr[run] = (uint16_t)i; run++; }
    }
    if (tid == 1023) g_nmin[img] = (int)run;
}

// ---------------- 7) emit crossing edges as (w | cu_dense | cv_dense) -------
__global__ void k_edges() {
    int i = blockIdx.x * blockDim.x + threadIdx.x;
    if (i >= NIMG * NPIX) return;
    int img = i >> 16;
    uint32_t r = (uint32_t)(i & (NPIX - 1));
    const uint16_t* bs = g_basin + ((size_t)img << 16);
    const uint16_t* dn = g_dense + ((size_t)img << 16);
    unsigned long long w = g_nbrs[i];
    uint32_t br = bs[r];

    unsigned long long recs[3];
    int cnt = 0;
    #pragma unroll
    for (int k = 0; k < 4; k++) {
        uint32_t q = (uint32_t)(w >> (k * 16)) & 0xFFFFu;
        if (q < r) {
            uint32_t bq = bs[q];
            if (bq != br)
                recs[cnt++] = ((unsigned long long)r << 32)
                            | ((unsigned long long)dn[br] << 16)
                            | (unsigned long long)dn[bq];
        }
    }
    int lane = threadIdx.x & 31;
    int pre = cnt;
    #pragma unroll
    for (int o = 1; o < 32; o <<= 1) {
        int n = __shfl_up_sync(0xFFFFFFFFu, pre, o);
        if (lane >= o) pre += n;
    }
    int total = __shfl_sync(0xFFFFFFFFu, pre, 31);
    int excl = pre - cnt;
    int base = 0;
    if (lane == 31 && total > 0) base = atomicAdd(&g_ecnt[img], total);
    base = __shfl_sync(0xFFFFFFFFu, base, 31);
    unsigned long long* er = g_edges + (size_t)img * EMAX;
    for (int j = 0; j < cnt; j++) er[base + excl + j] = recs[j];
}

// ---------------- 8) parallel Boruvka MST on the basin graph ----------------
// sel key = (w<<16)|other: a cycle of hooks forces equal w and contradictory
// id orderings except mutual 2-cycles, which the "larger id hooks" rule breaks.
// Mutual selections provably share the same w, so either edge is MST-valid.
__global__ void __launch_bounds__(1024, 1) k_boruvka() {
    extern __shared__ char smraw[];
    uint16_t* par = (uint16_t*)smraw;              // 64 KB (32768 u16)
    uint32_t* sel = (uint32_t*)(smraw + 65536);    // 128 KB (32768 u32)
    __shared__ int s_hooks;
    const int img = blockIdx.x, tid = threadIdx.x;
    const int nmin = g_nmin[img];
    const int m = g_ecnt[img];
    unsigned long long* ed  = g_edges + (size_t)img * EMAX;
    unsigned long long* mst = g_mstA  + (size_t)img * PMAX;

    for (int i = tid; i < nmin; i += 1024) par[i] = (uint16_t)i;

    for (int round = 0; round < 17; round++) {
        if (tid == 0) s_hooks = 0;
        for (int i = tid; i < nmin; i += 1024) sel[i] = 0xFFFFFFFFu;
        __syncthreads();

        // select lightest incident edge per component
        for (int i = tid; i < m; i += 1024) {
            unsigned long long e = ed[i];
            uint32_t lo = (uint32_t)e;
            uint32_t cu = lo >> 16, cv = lo & 0xFFFFu;
            if (cu == cv) continue;
            uint32_t w = (uint32_t)(e >> 32);
            atomicMin(&sel[cu], (w << 16) | cv);
            atomicMin(&sel[cv], (w << 16) | cu);
        }
        __syncthreads();

        // hook (larger id yields in mutual pairs) + record MST edge
        for (int c = tid; c < nmin; c += 1024) {
            uint32_t s = sel[c];
            if (s == 0xFFFFFFFFu) continue;
            uint32_t d = s & 0xFFFFu;
            uint32_t sd = sel[d];
            bool mutual = ((sd & 0xFFFFu) == (uint32_t)c);
            if (mutual && (uint32_t)c < d) continue;    // smaller stays root
            par[c] = (uint16_t)d;
            int pos = atomicAdd(&g_mcnt[img], 1);
            mst[pos] = ((unsigned long long)(s >> 16) << 32)
                     | ((unsigned long long)c << 16) | (unsigned long long)d;
            s_hooks = 1;
        }
        __syncthreads();
        if (s_hooks == 0) break;

        // full flatten: 16 pointer-doubling sweeps cover any depth <= 65536
        for (int it = 0; it < 16; it++) {
            for (int i = tid; i < nmin; i += 1024) par[i] = par[par[i]];
            __syncthreads();
        }

        // relabel edge endpoints with root ids
        for (int i = tid; i < m; i += 1024) {
            unsigned long long e = ed[i];
            uint32_t lo = (uint32_t)e;
            uint32_t cu = lo >> 16, cv = lo & 0xFFFFu;
            if (cu == cv) continue;
            cu = par[cu]; cv = par[cv];
            ed[i] = (e & 0xFFFFFFFF00000000ull)
                  | ((unsigned long long)cu << 16) | (unsigned long long)cv;
        }
        __syncthreads();
    }
}

// ---------------- 9) radix sort MST edges by death rank (bits [32,48)) ------
__global__ void __launch_bounds__(1024, 1) k_mstsort() {
    extern __shared__ uint32_t hist[];          // 64 KB
    __shared__ uint32_t warpsum[32];
    const int img  = blockIdx.x;
    const int tid  = threadIdx.x;
    const int lane = tid & 31;
    const int wid  = tid >> 5;
    const int n = g_mcnt[img];
    const size_t off = (size_t)img * PMAX;

    for (int pass = 0; pass < 4; pass++) {
        const unsigned long long* src = (pass & 1) ? g_mstB + off : g_mstA + off;
        unsigned long long*       dst = (pass & 1) ? g_mstA + off : g_mstB + off;
        const int shift = 32 + pass * 4;

        #pragma unroll
        for (int i = 0; i < 16; i++) hist[i * 1024 + tid] = 0;
        __syncthreads();

        const int base = tid * 32;
        for (int j = 0; j < 32; j++) {
            int idx = base + j;
            if (idx < n) {
                uint32_t d = (uint32_t)(src[idx] >> shift) & 15u;
                hist[(d << 10) + tid]++;
            }
        }
        __syncthreads();

        const int sb = tid * 16;
        uint32_t sum = 0;
        #pragma unroll
        for (int i = 0; i < 16; i++) sum += hist[sb + i];
        uint32_t v = sum;
        #pragma unroll
        for (int o = 1; o < 32; o <<= 1) {
            uint32_t t = __shfl_up_sync(0xFFFFFFFFu, v, o);
            if (lane >= o) v += t;
        }
        if (lane == 31) warpsum[wid] = v;
        __syncthreads();
        if (wid == 0) {
            uint32_t w  = warpsum[lane];
            uint32_t wv = w;
            #pragma unroll
            for (int o = 1; o < 32; o <<= 1) {
                uint32_t t = __shfl_up_sync(0xFFFFFFFFu, wv, o);
                if (lane >= o) wv += t;
            }
            warpsum[lane] = wv - w;
        }
        __syncthreads();
        uint32_t run = (v - sum) + warpsum[wid];
        #pragma unroll
        for (int i = 0; i < 16; i++) { uint32_t t = hist[sb + i]; hist[sb + i] = run; run += t; }
        __syncthreads();

        for (int j = 0; j < 32; j++) {
            int idx = base + j;
            if (idx < n) {
                unsigned long long k = src[idx];
                uint32_t d = (uint32_t)(k >> shift) & 15u;
                dst[hist[(d << 10) + tid]++] = k;
            }
        }
        __syncthreads();
    }
}

// ---------------- 10) serial pairing over sorted MST edges ------------------
__device__ __forceinline__ uint32_t uf_find(uint16_t* par, uint32_t x) {
    uint32_t p = par[x];
    while (p != x) {                 // path halving
        uint32_t g = par[p];
        par[x] = (uint16_t)g;
        x = g;
        p = par[x];
    }
    return x;
}

__global__ void __launch_bounds__(1024, 1) k_pair() {
    extern __shared__ uint16_t par[];            // 64 KB
    const int img = blockIdx.x;
    const int tid = threadIdx.x;
    const int nmin = g_nmin[img];
    for (int i = tid; i < nmin; i += 1024) par[i] = (uint16_t)i;
    __syncthreads();
    if (tid != 0) return;

    const unsigned long long* __restrict__ mst = g_mstA + (size_t)img * PMAX;
    uint32_t* __restrict__ out = g_pairs + (size_t)img * PMAX;
    const int m = g_mcnt[img];

    int pc = 0;
    for (int i = 0; i < m; i++) {
        unsigned long long e = mst[i];
        uint32_t cu = ((uint32_t)e) >> 16, cv = (uint32_t)e & 0xFFFFu;
        uint32_t ru = uf_find(par, cu);
        uint32_t rv = uf_find(par, cv);
        if (ru == rv) continue;                  // defensive; MST has no cycles
        uint32_t die  = ru > rv ? ru : rv;       // younger = larger dense id
        uint32_t keep = ru > rv ? rv : ru;
        par[die] = (uint16_t)keep;
        out[pc++] = (((uint32_t)(e >> 32)) << 16) | die;   // death rank | dying id
    }
    g_pcnt[img] = pc;
}

// ---------------- 11) parallel top-5 lifetimes + per-image loss -------------
__device__ __forceinline__ void top5_ins(float& t0, float& t1, float& t2,
                                         float& t3, float& t4, float life) {
    if (life <= t4) return;
    if (life > t0)      { t4 = t3; t3 = t2; t2 = t1; t1 = t0; t0 = life; }
    else if (life > t1) { t4 = t3; t3 = t2; t2 = t1; t1 = life; }
    else if (life > t2) { t4 = t3; t3 = t2; t2 = life; }
    else if (life > t3) { t4 = t3; t3 = life; }
    else                  t4 = life;
}

__global__ void __launch_bounds__(1024, 1) k_top() {
    __shared__ float cand[1024 * 5];
    const int img = blockIdx.x;
    const int tid = threadIdx.x;
    const uint32_t* __restrict__ pr = g_pairs + (size_t)img * PMAX;
    const uint16_t* __restrict__ mr = g_minrank + (size_t)img * PMAX;
    const float* __restrict__ sf = g_sortedf + ((size_t)img << 16);
    const int m = g_pcnt[img];

    float t0 = -1e30f, t1 = -1e30f, t2 = -1e30f, t3 = -1e30f, t4 = -1e30f;
    for (int i = tid; i < m; i += 1024) {
        uint32_t e = pr[i];
        float life = sf[e >> 16] - sf[mr[e & 0xFFFFu]];
        top5_ins(t0, t1, t2, t3, t4, life);
    }
    cand[tid * 5 + 0] = t0; cand[tid * 5 + 1] = t1; cand[tid * 5 + 2] = t2;
    cand[tid * 5 + 3] = t3; cand[tid * 5 + 4] = t4;
    __syncthreads();
    if (tid == 0) {
        float s0 = -1e30f, s1 = -1e30f, s2 = -1e30f, s3 = -1e30f, s4 = -1e30f;
        for (int i = 0; i < 1024 * 5; i++) top5_ins(s0, s1, s2, s3, s4, cand[i]);
        if (s0 < -1e29f) s0 = 0.0f;
        if (s1 < -1e29f) s1 = 0.0f;
        if (s2 < -1e29f) s2 = 0.0f;
        if (s3 < -1e29f) s3 = 0.0f;
        if (s4 < -1e29f) s4 = 0.0f;
        float d0 = s0 - 0.5f, d1 = s1 - 0.5f, d2 = s2 - 0.5f, d3 = s3 - 0.5f, d4 = s4 - 0.5f;
        g_loss[img] = (d0 * d0 + d1 * d1 + d2 * d2 + d3 * d3 + d4 * d4) * 0.2f;
    }
}

__global__ void k_final(float* out) {
    out[0] = (g_loss[0] + g_loss[1] + g_loss[2] + g_loss[3]) * 25.0f; // mean/4 * 100
}

// ---------------- launch -----------------------------------------------------
extern "C" void kernel_launch(void* const* d_in, const int* in_sizes, int n_in,
                              void* d_out, int out_size) {
    (void)in_sizes; (void)n_in; (void)out_size;
    const float* prob = (const float*)d_in[0];
    const float* roi  = (const float*)d_in[1];
    float* out = (float*)d_out;

    cudaFuncSetAttribute(k_radix,   cudaFuncAttributeMaxDynamicSharedMemorySize, 64 * 1024);
    cudaFuncSetAttribute(k_mstsort, cudaFuncAttributeMaxDynamicSharedMemorySize, 64 * 1024);
    cudaFuncSetAttribute(k_basin,   cudaFuncAttributeMaxDynamicSharedMemorySize, NPIX * 2);
    cudaFuncSetAttribute(k_boruvka, cudaFuncAttributeMaxDynamicSharedMemorySize, 192 * 1024);
    cudaFuncSetAttribute(k_pair,    cudaFuncAttributeMaxDynamicSharedMemorySize, 64 * 1024);

    const int nTot = NIMG * NPIX;
    k_init<<<(nTot + 255) / 256, 256>>>(prob, roi);
    k_radix<<<NIMG, 1024, 64 * 1024>>>();
    k_rank<<<(nTot + 255) / 256, 256>>>();
    k_nbr<<<(nTot + 255) / 256, 256>>>();
    k_basin<<<NIMG, 1024, NPIX * 2>>>();
    k_dense<<<NIMG, 1024>>>();
    k_edges<<<(nTot + 255) / 256, 256>>>();
    k_boruvka<<<NIMG, 1024, 192 * 1024>>>();
    k_mstsort<<<NIMG, 1024, 64 * 1024>>>();
    k_pair<<<NIMG, 1024, 64 * 1024>>>();
    k_top<<<NIMG, 1024>>>();
    k_final<<<1, 1>>>(out);
}

// round 4
// speedup vs baseline: 4.6278x; 1.0053x over previous
#include <cuda_runtime.h>
#include <stdint.h>

#define NPIX 65536
#define NIMG 4
#define EMAX 131072            // >= 2*256*255 edges per image
#define PMAX 32768             // max #local minima (independent set bound)

// ---------------- device scratch (no allocations allowed) ----------------
__device__ uint32_t g_keyA[NIMG * NPIX];
__device__ uint32_t g_keyB[NIMG * NPIX];
__device__ uint32_t g_payA[NIMG * NPIX];
__device__ uint32_t g_payB[NIMG * NPIX];
__device__ float    g_fval[NIMG * NPIX];
__device__ uint16_t g_rank16[NIMG * NPIX];
__device__ float    g_sortedf[NIMG * NPIX];
__device__ unsigned long long g_nbrs[NIMG * NPIX];
__device__ uint16_t g_basin[NIMG * NPIX];
__device__ uint16_t g_dense[NIMG * NPIX];
__device__ uint16_t g_minrank[NIMG * PMAX];
__device__ int      g_nmin[NIMG];
__device__ unsigned long long g_edges[NIMG * EMAX];
__device__ int      g_ecnt[NIMG];
__device__ unsigned long long g_mstA[NIMG * PMAX];
__device__ unsigned long long g_mstB[NIMG * PMAX];
__device__ int      g_mcnt[NIMG];
__device__ uint32_t g_pairs[NIMG * PMAX];
__device__ int      g_pcnt[NIMG];
__device__ float    g_loss[NIMG];

// ---------------- 1) f = 1 - prob*roi, keys = float bits --------------------
__global__ void k_init(const float* __restrict__ prob, const float* __restrict__ roi) {
    int i = blockIdx.x * blockDim.x + threadIdx.x;
    if (i < NIMG) { g_ecnt[i] = 0; g_mcnt[i] = 0; }
    if (i < NIMG * NPIX) {
        float f = 1.0f - prob[i] * roi[i];
        g_fval[i] = f;
        g_keyA[i] = __float_as_uint(f);   // f>0 -> bit order == float order
        g_payA[i] = (uint32_t)(i & (NPIX - 1));
    }
}

// ---------------- 2) per-image stable LSD radix sort (8 x 4-bit) ------------
__global__ void __launch_bounds__(1024, 1) k_radix() {
    extern __shared__ uint32_t hist[];          // 64 KB
    __shared__ uint32_t warpsum[32];
    const int img  = blockIdx.x;
    const int tid  = threadIdx.x;
    const int lane = tid & 31;
    const int wid  = tid >> 5;
    const uint32_t off = (uint32_t)img * NPIX;

    for (int pass = 0; pass < 8; pass++) {
        uint32_t *src, *dst, *ps, *pd;
        if (pass & 1) { src = g_keyB; dst = g_keyA; ps = g_payB; pd = g_payA; }
        else          { src = g_keyA; dst = g_keyB; ps = g_payA; pd = g_payB; }
        src += off; dst += off; ps += off; pd += off;
        const int shift = pass * 4;

        #pragma unroll
        for (int i = 0; i < 16; i++) hist[i * 1024 + tid] = 0;
        __syncthreads();

        const int base = tid * 64;
        for (int j = 0; j < 64; j++) {
            uint32_t d = (src[base + j] >> shift) & 15u;
            hist[(d << 10) + tid]++;
        }
        __syncthreads();

        const int sb = tid * 16;
        uint32_t sum = 0;
        #pragma unroll
        for (int i = 0; i < 16; i++) sum += hist[sb + i];
        uint32_t v = sum;
        #pragma unroll
        for (int o = 1; o < 32; o <<= 1) {
            uint32_t n = __shfl_up_sync(0xFFFFFFFFu, v, o);
            if (lane >= o) v += n;
        }
        if (lane == 31) warpsum[wid] = v;
        __syncthreads();
        if (wid == 0) {
            uint32_t w  = warpsum[lane];
            uint32_t wv = w;
            #pragma unroll
            for (int o = 1; o < 32; o <<= 1) {
                uint32_t n = __shfl_up_sync(0xFFFFFFFFu, wv, o);
                if (lane >= o) wv += n;
            }
            warpsum[lane] = wv - w;
        }
        __syncthreads();
        uint32_t run = (v - sum) + warpsum[wid];
        #pragma unroll
        for (int i = 0; i < 16; i++) { uint32_t t = hist[sb + i]; hist[sb + i] = run; run += t; }
        __syncthreads();

        for (int j = 0; j < 64; j++) {
            uint32_t k = src[base + j];
            uint32_t d = (k >> shift) & 15u;
            uint32_t pos = hist[(d << 10) + tid]++;
            dst[pos] = k;
            pd[pos]  = ps[base + j];
        }
        __syncthreads();
    }
}

// ---------------- 3) rank (inverse perm) + f gathered in rank order ---------
__global__ void k_rank() {
    int i = blockIdx.x * blockDim.x + threadIdx.x;
    if (i < NIMG * NPIX) {
        int img = i >> 16;
        uint32_t pix = g_payA[i];
        g_rank16[(img << 16) + pix] = (uint16_t)(i & (NPIX - 1));
        g_sortedf[i] = g_fval[(img << 16) + pix];
    }
}

// ---------------- 4) packed neighbor ranks, indexed by rank -----------------
__global__ void k_nbr() {
    int i = blockIdx.x * blockDim.x + threadIdx.x;
    if (i < NIMG * NPIX) {
        int img = i >> 16;
        uint32_t pix = (uint32_t)(i & (NPIX - 1));
        const uint16_t* rk = g_rank16 + ((size_t)img << 16);
        uint32_t r = rk[pix];
        int y = pix >> 8, x = pix & 255;
        unsigned long long n0 = (y > 0)   ? (unsigned long long)rk[pix - 256] : 0xFFFFull;
        unsigned long long n1 = (y < 255) ? (unsigned long long)rk[pix + 256] : 0xFFFFull;
        unsigned long long n2 = (x > 0)   ? (unsigned long long)rk[pix - 1]   : 0xFFFFull;
        unsigned long long n3 = (x < 255) ? (unsigned long long)rk[pix + 1]   : 0xFFFFull;
        g_nbrs[((size_t)img << 16) + r] = n0 | (n1 << 16) | (n2 << 32) | (n3 << 48);
    }
}

// ---------------- 5) basins: steepest-descent forest + pointer doubling -----
__global__ void __launch_bounds__(1024, 1) k_basin() {
    extern __shared__ uint16_t bs[];             // 128 KB
    const int img = blockIdx.x;
    const int tid = threadIdx.x;
    const unsigned long long* __restrict__ nb = g_nbrs + ((size_t)img << 16);

    for (int i = tid; i < NPIX; i += 1024) {
        unsigned long long w = nb[i];
        uint32_t m0 = (uint32_t)(w & 0xFFFF), m1 = (uint32_t)((w >> 16) & 0xFFFF);
        uint32_t m2 = (uint32_t)((w >> 32) & 0xFFFF), m3 = (uint32_t)(w >> 48);
        uint32_t m = min(min(m0, m1), min(m2, m3));
        bs[i] = (uint16_t)((m < (uint32_t)i) ? m : (uint32_t)i);
    }
    __syncthreads();
    for (int round = 0; round < 16; round++) {
        for (int i = tid; i < NPIX; i += 1024) {
            uint32_t p = bs[i];
            bs[i] = bs[p];
        }
        __syncthreads();
    }
    uint16_t* out = g_basin + ((size_t)img << 16);
    for (int i = tid; i < NPIX; i += 1024) out[i] = bs[i];
}

// ---------------- 6) dense basin ids (ascending rank => ascending birth) ----
__global__ void __launch_bounds__(1024, 1) k_dense() {
    __shared__ uint32_t warpsum[32];
    const int img = blockIdx.x, tid = threadIdx.x;
    const int lane = tid & 31, wid = tid >> 5;
    const uint16_t* bs = g_basin + ((size_t)img << 16);
    const int base = tid * 64;

    uint32_t cnt = 0;
    for (int j = 0; j < 64; j++) cnt += (bs[base + j] == (uint16_t)(base + j));
    uint32_t v = cnt;
    #pragma unroll
    for (int o = 1; o < 32; o <<= 1) {
        uint32_t n = __shfl_up_sync(0xFFFFFFFFu, v, o);
        if (lane >= o) v += n;
    }
    if (lane == 31) warpsum[wid] = v;
    __syncthreads();
    if (wid == 0) {
        uint32_t w  = warpsum[lane];
        uint32_t wv = w;
        #pragma unroll
        for (int o = 1; o < 32; o <<= 1) {
            uint32_t n = __shfl_up_sync(0xFFFFFFFFu, wv, o);
            if (lane >= o) wv += n;
        }
        warpsum[lane] = wv - w;
    }
    __syncthreads();
    uint32_t run = (v - cnt) + warpsum[wid];
    uint16_t* dn = g_dense   + ((size_t)img << 16);
    uint16_t* mr = g_minrank + (size_t)img * PMAX;
    for (int j = 0; j < 64; j++) {
        int i = base + j;
        if (bs[i] == (uint16_t)i) { dn[i] = (uint16_t)run; mr[run] = (uint16_t)i; run++; }
    }
    if (tid == 1023) g_nmin[img] = (int)run;
}

// ---------------- 7) emit crossing edges as (w | cu_dense | cv_dense) -------
__global__ void k_edges() {
    int i = blockIdx.x * blockDim.x + threadIdx.x;
    if (i >= NIMG * NPIX) return;
    int img = i >> 16;
    uint32_t r = (uint32_t)(i & (NPIX - 1));
    const uint16_t* bs = g_basin + ((size_t)img << 16);
    const uint16_t* dn = g_dense + ((size_t)img << 16);
    unsigned long long w = g_nbrs[i];
    uint32_t br = bs[r];

    unsigned long long recs[3];
    int cnt = 0;
    #pragma unroll
    for (int k = 0; k < 4; k++) {
        uint32_t q = (uint32_t)(w >> (k * 16)) & 0xFFFFu;
        if (q < r) {
            uint32_t bq = bs[q];
            if (bq != br)
                recs[cnt++] = ((unsigned long long)r << 32)
                            | ((unsigned long long)dn[br] << 16)
                            | (unsigned long long)dn[bq];
        }
    }
    int lane = threadIdx.x & 31;
    int pre = cnt;
    #pragma unroll
    for (int o = 1; o < 32; o <<= 1) {
        int n = __shfl_up_sync(0xFFFFFFFFu, pre, o);
        if (lane >= o) pre += n;
    }
    int total = __shfl_sync(0xFFFFFFFFu, pre, 31);
    int excl = pre - cnt;
    int base = 0;
    if (lane == 31 && total > 0) base = atomicAdd(&g_ecnt[img], total);
    base = __shfl_sync(0xFFFFFFFFu, base, 31);
    unsigned long long* er = g_edges + (size_t)img * EMAX;
    for (int j = 0; j < cnt; j++) er[base + excl + j] = recs[j];
}

// ---------------- 8) parallel Boruvka MST on the basin graph ----------------
// sel key = (w<<16)|other: a cycle of hooks forces equal w and contradictory
// id orderings except mutual 2-cycles, which the "larger id hooks" rule breaks.
// Mutual selections provably share the same w, so either edge is MST-valid.
__global__ void __launch_bounds__(1024, 1) k_boruvka() {
    extern __shared__ char smraw[];
    uint16_t* par = (uint16_t*)smraw;              // 64 KB (32768 u16)
    uint32_t* sel = (uint32_t*)(smraw + 65536);    // 128 KB (32768 u32)
    __shared__ int s_hooks;
    const int img = blockIdx.x, tid = threadIdx.x;
    const int nmin = g_nmin[img];
    const int m = g_ecnt[img];
    unsigned long long* ed  = g_edges + (size_t)img * EMAX;
    unsigned long long* mst = g_mstA  + (size_t)img * PMAX;

    for (int i = tid; i < nmin; i += 1024) par[i] = (uint16_t)i;

    for (int round = 0; round < 17; round++) {
        if (tid == 0) s_hooks = 0;
        for (int i = tid; i < nmin; i += 1024) sel[i] = 0xFFFFFFFFu;
        __syncthreads();

        // select lightest incident edge per component
        for (int i = tid; i < m; i += 1024) {
            unsigned long long e = ed[i];
            uint32_t lo = (uint32_t)e;
            uint32_t cu = lo >> 16, cv = lo & 0xFFFFu;
            if (cu == cv) continue;
            uint32_t w = (uint32_t)(e >> 32);
            atomicMin(&sel[cu], (w << 16) | cv);
            atomicMin(&sel[cv], (w << 16) | cu);
        }
        __syncthreads();

        // hook (larger id yields in mutual pairs) + record MST edge
        for (int c = tid; c < nmin; c += 1024) {
            uint32_t s = sel[c];
            if (s == 0xFFFFFFFFu) continue;
            uint32_t d = s & 0xFFFFu;
            uint32_t sd = sel[d];
            bool mutual = ((sd & 0xFFFFu) == (uint32_t)c);
            if (mutual && (uint32_t)c < d) continue;    // smaller stays root
            par[c] = (uint16_t)d;
            int pos = atomicAdd(&g_mcnt[img], 1);
            mst[pos] = ((unsigned long long)(s >> 16) << 32)
                     | ((unsigned long long)c << 16) | (unsigned long long)d;
            s_hooks = 1;
        }
        __syncthreads();
        if (s_hooks == 0) break;

        // full flatten: 16 pointer-doubling sweeps cover any depth <= 65536
        for (int it = 0; it < 16; it++) {
            for (int i = tid; i < nmin; i += 1024) par[i] = par[par[i]];
            __syncthreads();
        }

        // relabel edge endpoints with root ids
        for (int i = tid; i < m; i += 1024) {
            unsigned long long e = ed[i];
            uint32_t lo = (uint32_t)e;
            uint32_t cu = lo >> 16, cv = lo & 0xFFFFu;
            if (cu == cv) continue;
            cu = par[cu]; cv = par[cv];
            ed[i] = (e & 0xFFFFFFFF00000000ull)
                  | ((unsigned long long)cu << 16) | (unsigned long long)cv;
        }
        __syncthreads();
    }
}

// ---------------- 9) radix sort MST edges by death rank (bits [32,48)) ------
__global__ void __launch_bounds__(1024, 1) k_mstsort() {
    extern __shared__ uint32_t hist[];          // 64 KB
    __shared__ uint32_t warpsum[32];
    const int img  = blockIdx.x;
    const int tid  = threadIdx.x;
    const int lane = tid & 31;
    const int wid  = tid >> 5;
    const int n = g_mcnt[img];
    const size_t off = (size_t)img * PMAX;

    for (int pass = 0; pass < 4; pass++) {
        const unsigned long long* src = (pass & 1) ? g_mstB + off : g_mstA + off;
        unsigned long long*       dst = (pass & 1) ? g_mstA + off : g_mstB + off;
        const int shift = 32 + pass * 4;

        #pragma unroll
        for (int i = 0; i < 16; i++) hist[i * 1024 + tid] = 0;
        __syncthreads();

        const int base = tid * 32;
        for (int j = 0; j < 32; j++) {
            int idx = base + j;
            if (idx < n) {
                uint32_t d = (uint32_t)(src[idx] >> shift) & 15u;
                hist[(d << 10) + tid]++;
            }
        }
        __syncthreads();

        const int sb = tid * 16;
        uint32_t sum = 0;
        #pragma unroll
        for (int i = 0; i < 16; i++) sum += hist[sb + i];
        uint32_t v = sum;
        #pragma unroll
        for (int o = 1; o < 32; o <<= 1) {
            uint32_t t = __shfl_up_sync(0xFFFFFFFFu, v, o);
            if (lane >= o) v += t;
        }
        if (lane == 31) warpsum[wid] = v;
        __syncthreads();
        if (wid == 0) {
            uint32_t w  = warpsum[lane];
            uint32_t wv = w;
            #pragma unroll
            for (int o = 1; o < 32; o <<= 1) {
                uint32_t t = __shfl_up_sync(0xFFFFFFFFu, wv, o);
                if (lane >= o) wv += t;
            }
            warpsum[lane] = wv - w;
        }
        __syncthreads();
        uint32_t run = (v - sum) + warpsum[wid];
        #pragma unroll
        for (int i = 0; i < 16; i++) { uint32_t t = hist[sb + i]; hist[sb + i] = run; run += t; }
        __syncthreads();

        for (int j = 0; j < 32; j++) {
            int idx = base + j;
            if (idx < n) {
                unsigned long long k = src[idx];
                uint32_t d = (uint32_t)(k >> shift) & 15u;
                dst[hist[(d << 10) + tid]++] = k;
            }
        }
        __syncthreads();
    }
}

// ---------------- 10) serial pairing over sorted MST edges ------------------
__device__ __forceinline__ uint32_t uf_find(uint16_t* par, uint32_t x) {
    uint32_t p = par[x];
    while (p != x) {                 // path halving
        uint32_t g = par[p];
        par[x] = (uint16_t)g;
        x = g;
        p = par[x];
    }
    return x;
}

__global__ void __launch_bounds__(1024, 1) k_pair() {
    extern __shared__ uint16_t par[];            // 64 KB
    const int img = blockIdx.x;
    const int tid = threadIdx.x;
    const int nmin = g_nmin[img];
    for (int i = tid; i < nmin; i += 1024) par[i] = (uint16_t)i;
    __syncthreads();
    if (tid != 0) return;

    const unsigned long long* __restrict__ mst = g_mstA + (size_t)img * PMAX;
    uint32_t* __restrict__ out = g_pairs + (size_t)img * PMAX;
    const int m = g_mcnt[img];

    int pc = 0;
    for (int i = 0; i < m; i++) {
        unsigned long long e = mst[i];
        uint32_t cu = ((uint32_t)e) >> 16, cv = (uint32_t)e & 0xFFFFu;
        uint32_t ru = uf_find(par, cu);
        uint32_t rv = uf_find(par, cv);
        if (ru == rv) continue;                  // defensive; MST has no cycles
        uint32_t die  = ru > rv ? ru : rv;       // younger = larger dense id
        uint32_t keep = ru > rv ? rv : ru;
        par[die] = (uint16_t)keep;
        out[pc++] = (((uint32_t)(e >> 32)) << 16) | die;   // death rank | dying id
    }
    g_pcnt[img] = pc;
}

// ---------------- 11) parallel top-5 lifetimes + per-image loss -------------
__device__ __forceinline__ void top5_ins(float& t0, float& t1, float& t2,
                                         float& t3, float& t4, float life) {
    if (life <= t4) return;
    if (life > t0)      { t4 = t3; t3 = t2; t2 = t1; t1 = t0; t0 = life; }
    else if (life > t1) { t4 = t3; t3 = t2; t2 = t1; t1 = life; }
    else if (life > t2) { t4 = t3; t3 = t2; t2 = life; }
    else if (life > t3) { t4 = t3; t3 = life; }
    else                  t4 = life;
}

__global__ void __launch_bounds__(1024, 1) k_top() {
    __shared__ float cand[1024 * 5];
    const int img = blockIdx.x;
    const int tid = threadIdx.x;
    const uint32_t* __restrict__ pr = g_pairs + (size_t)img * PMAX;
    const uint16_t* __restrict__ mr = g_minrank + (size_t)img * PMAX;
    const float* __restrict__ sf = g_sortedf + ((size_t)img << 16);
    const int m = g_pcnt[img];

    float t0 = -1e30f, t1 = -1e30f, t2 = -1e30f, t3 = -1e30f, t4 = -1e30f;
    for (int i = tid; i < m; i += 1024) {
        uint32_t e = pr[i];
        float life = sf[e >> 16] - sf[mr[e & 0xFFFFu]];
        top5_ins(t0, t1, t2, t3, t4, life);
    }
    cand[tid * 5 + 0] = t0; cand[tid * 5 + 1] = t1; cand[tid * 5 + 2] = t2;
    cand[tid * 5 + 3] = t3; cand[tid * 5 + 4] = t4;
    __syncthreads();
    if (tid == 0) {
        float s0 = -1e30f, s1 = -1e30f, s2 = -1e30f, s3 = -1e30f, s4 = -1e30f;
        for (int i = 0; i < 1024 * 5; i++) top5_ins(s0, s1, s2, s3, s4, cand[i]);
        if (s0 < -1e29f) s0 = 0.0f;
        if (s1 < -1e29f) s1 = 0.0f;
        if (s2 < -1e29f) s2 = 0.0f;
        if (s3 < -1e29f) s3 = 0.0f;
        if (s4 < -1e29f) s4 = 0.0f;
        float d0 = s0 - 0.5f, d1 = s1 - 0.5f, d2 = s2 - 0.5f, d3 = s3 - 0.5f, d4 = s4 - 0.5f;
        g_loss[img] = (d0 * d0 + d1 * d1 + d2 * d2 + d3 * d3 + d4 * d4) * 0.2f;
    }
}

__global__ void k_final(float* out) {
    out[0] = (g_loss[0] + g_loss[1] + g_loss[2] + g_loss[3]) * 25.0f; // mean/4 * 100
}

// ---------------- launch -----------------------------------------------------
extern "C" void kernel_launch(void* const* d_in, const int* in_sizes, int n_in,
                              void* d_out, int out_size) {
    (void)in_sizes; (void)n_in; (void)out_size;
    const float* prob = (const float*)d_in[0];
    const float* roi  = (const float*)d_in[1];
    float* out = (float*)d_out;

    cudaFuncSetAttribute(k_radix,   cudaFuncAttributeMaxDynamicSharedMemorySize, 64 * 1024);
    cudaFuncSetAttribute(k_mstsort, cudaFuncAttributeMaxDynamicSharedMemorySize, 64 * 1024);
    cudaFuncSetAttribute(k_basin,   cudaFuncAttributeMaxDynamicSharedMemorySize, NPIX * 2);
    cudaFuncSetAttribute(k_boruvka, cudaFuncAttributeMaxDynamicSharedMemorySize, 192 * 1024);
    cudaFuncSetAttribute(k_pair,    cudaFuncAttributeMaxDynamicSharedMemorySize, 64 * 1024);

    const int nTot = NIMG * NPIX;
    k_init<<<(nTot + 255) / 256, 256>>>(prob, roi);
    k_radix<<<NIMG, 1024, 64 * 1024>>>();
    k_rank<<<(nTot + 255) / 256, 256>>>();
    k_nbr<<<(nTot + 255) / 256, 256>>>();
    k_basin<<<NIMG, 1024, NPIX * 2>>>();
    k_dense<<<NIMG, 1024>>>();
    k_edges<<<(nTot + 255) / 256, 256>>>();
    k_boruvka<<<NIMG, 1024, 192 * 1024>>>();
    k_mstsort<<<NIMG, 1024, 64 * 1024>>>();
    k_pair<<<NIMG, 1024, 64 * 1024>>>();
    k_top<<<NIMG, 1024>>>();
    k_final<<<1, 1>>>(out);
}

// round 5
// speedup vs baseline: 4.6289x; 1.0002x over previous
#include <cuda_runtime.h>
#include <stdint.h>

#define NPIX 65536
#define NIMG 4
#define EMAX 131072            // >= 2*256*255 edges per image
#define PMAX 32768             // max #local minima (independent set bound)

// ---------------- device scratch (no allocations allowed) ----------------
__device__ uint32_t g_keyA[NIMG * NPIX];
__device__ uint32_t g_keyB[NIMG * NPIX];
__device__ uint32_t g_payA[NIMG * NPIX];
__device__ uint32_t g_payB[NIMG * NPIX];
__device__ float    g_fval[NIMG * NPIX];
__device__ uint16_t g_rank16[NIMG * NPIX];
__device__ float    g_sortedf[NIMG * NPIX];
__device__ unsigned long long g_nbrs[NIMG * NPIX];
__device__ uint16_t g_basin[NIMG * NPIX];
__device__ uint16_t g_dense[NIMG * NPIX];
__device__ uint16_t g_minrank[NIMG * PMAX];
__device__ int      g_nmin[NIMG];
__device__ unsigned long long g_edges[NIMG * EMAX];
__device__ int      g_ecnt[NIMG];
__device__ unsigned long long g_mstA[NIMG * PMAX];
__device__ unsigned long long g_mstB[NIMG * PMAX];
__device__ int      g_mcnt[NIMG];
__device__ uint32_t g_pairs[NIMG * PMAX];
__device__ int      g_pcnt[NIMG];
__device__ float    g_loss[NIMG];

// ---------------- 1) f = 1 - prob*roi, keys = float bits --------------------
__global__ void k_init(const float* __restrict__ prob, const float* __restrict__ roi) {
    int i = blockIdx.x * blockDim.x + threadIdx.x;
    if (i < NIMG) { g_ecnt[i] = 0; g_mcnt[i] = 0; }
    if (i < NIMG * NPIX) {
        float f = 1.0f - prob[i] * roi[i];
        g_fval[i] = f;
        g_keyA[i] = __float_as_uint(f);   // f>0 -> bit order == float order
        g_payA[i] = (uint32_t)(i & (NPIX - 1));
    }
}

// ---------------- 2) per-image stable LSD radix sort (8 x 4-bit) ------------
__global__ void __launch_bounds__(1024, 1) k_radix() {
    extern __shared__ uint32_t hist[];          // 64 KB
    __shared__ uint32_t warpsum[32];
    const int img  = blockIdx.x;
    const int tid  = threadIdx.x;
    const int lane = tid & 31;
    const int wid  = tid >> 5;
    const uint32_t off = (uint32_t)img * NPIX;

    for (int pass = 0; pass < 8; pass++) {
        uint32_t *src, *dst, *ps, *pd;
        if (pass & 1) { src = g_keyB; dst = g_keyA; ps = g_payB; pd = g_payA; }
        else          { src = g_keyA; dst = g_keyB; ps = g_payA; pd = g_payB; }
        src += off; dst += off; ps += off; pd += off;
        const int shift = pass * 4;

        #pragma unroll
        for (int i = 0; i < 16; i++) hist[i * 1024 + tid] = 0;
        __syncthreads();

        const int base = tid * 64;
        for (int j = 0; j < 64; j++) {
            uint32_t d = (src[base + j] >> shift) & 15u;
            hist[(d << 10) + tid]++;
        }
        __syncthreads();

        const int sb = tid * 16;
        uint32_t sum = 0;
        #pragma unroll
        for (int i = 0; i < 16; i++) sum += hist[sb + i];
        uint32_t v = sum;
        #pragma unroll
        for (int o = 1; o < 32; o <<= 1) {
            uint32_t n = __shfl_up_sync(0xFFFFFFFFu, v, o);
            if (lane >= o) v += n;
        }
        if (lane == 31) warpsum[wid] = v;
        __syncthreads();
        if (wid == 0) {
            uint32_t w  = warpsum[lane];
            uint32_t wv = w;
            #pragma unroll
            for (int o = 1; o < 32; o <<= 1) {
                uint32_t n = __shfl_up_sync(0xFFFFFFFFu, wv, o);
                if (lane >= o) wv += n;
            }
            warpsum[lane] = wv - w;
        }
        __syncthreads();
        uint32_t run = (v - sum) + warpsum[wid];
        #pragma unroll
        for (int i = 0; i < 16; i++) { uint32_t t = hist[sb + i]; hist[sb + i] = run; run += t; }
        __syncthreads();

        for (int j = 0; j < 64; j++) {
            uint32_t k = src[base + j];
            uint32_t d = (k >> shift) & 15u;
            uint32_t pos = hist[(d << 10) + tid]++;
            dst[pos] = k;
            pd[pos]  = ps[base + j];
        }
        __syncthreads();
    }
}

// ---------------- 3) rank (inverse perm) + f gathered in rank order ---------
__global__ void k_rank() {
    int i = blockIdx.x * blockDim.x + threadIdx.x;
    if (i < NIMG * NPIX) {
        int img = i >> 16;
        uint32_t pix = g_payA[i];
        g_rank16[(img << 16) + pix] = (uint16_t)(i & (NPIX - 1));
        g_sortedf[i] = g_fval[(img << 16) + pix];
    }
}

// ---------------- 4) packed neighbor ranks, indexed by rank -----------------
__global__ void k_nbr() {
    int i = blockIdx.x * blockDim.x + threadIdx.x;
    if (i < NIMG * NPIX) {
        int img = i >> 16;
        uint32_t pix = (uint32_t)(i & (NPIX - 1));
        const uint16_t* rk = g_rank16 + ((size_t)img << 16);
        uint32_t r = rk[pix];
        int y = pix >> 8, x = pix & 255;
        unsigned long long n0 = (y > 0)   ? (unsigned long long)rk[pix - 256] : 0xFFFFull;
        unsigned long long n1 = (y < 255) ? (unsigned long long)rk[pix + 256] : 0xFFFFull;
        unsigned long long n2 = (x > 0)   ? (unsigned long long)rk[pix - 1]   : 0xFFFFull;
        unsigned long long n3 = (x < 255) ? (unsigned long long)rk[pix + 1]   : 0xFFFFull;
        g_nbrs[((size_t)img << 16) + r] = n0 | (n1 << 16) | (n2 << 32) | (n3 << 48);
    }
}

// ---------------- 5) basins: steepest-descent forest + pointer doubling -----
__global__ void __launch_bounds__(1024, 1) k_basin() {
    extern __shared__ uint16_t bs[];             // 128 KB
    const int img = blockIdx.x;
    const int tid = threadIdx.x;
    const unsigned long long* __restrict__ nb = g_nbrs + ((size_t)img << 16);

    for (int i = tid; i < NPIX; i += 1024) {
        unsigned long long w = nb[i];
        uint32_t m0 = (uint32_t)(w & 0xFFFF), m1 = (uint32_t)((w >> 16) & 0xFFFF);
        uint32_t m2 = (uint32_t)((w >> 32) & 0xFFFF), m3 = (uint32_t)(w >> 48);
        uint32_t m = min(min(m0, m1), min(m2, m3));
        bs[i] = (uint16_t)((m < (uint32_t)i) ? m : (uint32_t)i);
    }
    __syncthreads();
    for (int round = 0; round < 16; round++) {
        for (int i = tid; i < NPIX; i += 1024) {
            uint32_t p = bs[i];
            bs[i] = bs[p];
        }
        __syncthreads();
    }
    uint16_t* out = g_basin + ((size_t)img << 16);
    for (int i = tid; i < NPIX; i += 1024) out[i] = bs[i];
}

// ---------------- 6) dense basin ids (ascending rank => ascending birth) ----
__global__ void __launch_bounds__(1024, 1) k_dense() {
    __shared__ uint32_t warpsum[32];
    const int img = blockIdx.x, tid = threadIdx.x;
    const int lane = tid & 31, wid = tid >> 5;
    const uint16_t* bs = g_basin + ((size_t)img << 16);
    const int base = tid * 64;

    uint32_t cnt = 0;
    for (int j = 0; j < 64; j++) cnt += (bs[base + j] == (uint16_t)(base + j));
    uint32_t v = cnt;
    #pragma unroll
    for (int o = 1; o < 32; o <<= 1) {
        uint32_t n = __shfl_up_sync(0xFFFFFFFFu, v, o);
        if (lane >= o) v += n;
    }
    if (lane == 31) warpsum[wid] = v;
    __syncthreads();
    if (wid == 0) {
        uint32_t w  = warpsum[lane];
        uint32_t wv = w;
        #pragma unroll
        for (int o = 1; o < 32; o <<= 1) {
            uint32_t n = __shfl_up_sync(0xFFFFFFFFu, wv, o);
            if (lane >= o) wv += n;
        }
        warpsum[lane] = wv - w;
    }
    __syncthreads();
    uint32_t run = (v - cnt) + warpsum[wid];
    uint16_t* dn = g_dense   + ((size_t)img << 16);
    uint16_t* mr = g_minrank + (size_t)img * PMAX;
    for (int j = 0; j < 64; j++) {
        int i = base + j;
        if (bs[i] == (uint16_t)i) { dn[i] = (uint16_t)run; mr[run] = (uint16_t)i; run++; }
    }
    if (tid == 1023) g_nmin[img] = (int)run;
}

// ---------------- 7) emit crossing edges as (w | cu_dense | cv_dense) -------
__global__ void k_edges() {
    int i = blockIdx.x * blockDim.x + threadIdx.x;
    if (i >= NIMG * NPIX) return;
    int img = i >> 16;
    uint32_t r = (uint32_t)(i & (NPIX - 1));
    const uint16_t* bs = g_basin + ((size_t)img << 16);
    const uint16_t* dn = g_dense + ((size_t)img << 16);
    unsigned long long w = g_nbrs[i];
    uint32_t br = bs[r];

    unsigned long long recs[3];
    int cnt = 0;
    #pragma unroll
    for (int k = 0; k < 4; k++) {
        uint32_t q = (uint32_t)(w >> (k * 16)) & 0xFFFFu;
        if (q < r) {
            uint32_t bq = bs[q];
            if (bq != br)
                recs[cnt++] = ((unsigned long long)r << 32)
                            | ((unsigned long long)dn[br] << 16)
                            | (unsigned long long)dn[bq];
        }
    }
    int lane = threadIdx.x & 31;
    int pre = cnt;
    #pragma unroll
    for (int o = 1; o < 32; o <<= 1) {
        int n = __shfl_up_sync(0xFFFFFFFFu, pre, o);
        if (lane >= o) pre += n;
    }
    int total = __shfl_sync(0xFFFFFFFFu, pre, 31);
    int excl = pre - cnt;
    int base = 0;
    if (lane == 31 && total > 0) base = atomicAdd(&g_ecnt[img], total);
    base = __shfl_sync(0xFFFFFFFFu, base, 31);
    unsigned long long* er = g_edges + (size_t)img * EMAX;
    for (int j = 0; j < cnt; j++) er[base + excl + j] = recs[j];
}

// ---------------- 8) parallel Boruvka MST on the basin graph ----------------
// sel key = (w<<16)|other: a cycle of hooks forces equal w and contradictory
// id orderings except mutual 2-cycles, which the "larger id hooks" rule breaks.
// Mutual selections provably share the same w, so either edge is MST-valid.
__global__ void __launch_bounds__(1024, 1) k_boruvka() {
    extern __shared__ char smraw[];
    uint16_t* par = (uint16_t*)smraw;              // 64 KB (32768 u16)
    uint32_t* sel = (uint32_t*)(smraw + 65536);    // 128 KB (32768 u32)
    __shared__ int s_hooks;
    const int img = blockIdx.x, tid = threadIdx.x;
    const int nmin = g_nmin[img];
    const int m = g_ecnt[img];
    unsigned long long* ed  = g_edges + (size_t)img * EMAX;
    unsigned long long* mst = g_mstA  + (size_t)img * PMAX;

    for (int i = tid; i < nmin; i += 1024) par[i] = (uint16_t)i;

    for (int round = 0; round < 17; round++) {
        if (tid == 0) s_hooks = 0;
        for (int i = tid; i < nmin; i += 1024) sel[i] = 0xFFFFFFFFu;
        __syncthreads();

        // select lightest incident edge per component
        for (int i = tid; i < m; i += 1024) {
            unsigned long long e = ed[i];
            uint32_t lo = (uint32_t)e;
            uint32_t cu = lo >> 16, cv = lo & 0xFFFFu;
            if (cu == cv) continue;
            uint32_t w = (uint32_t)(e >> 32);
            atomicMin(&sel[cu], (w << 16) | cv);
            atomicMin(&sel[cv], (w << 16) | cu);
        }
        __syncthreads();

        // hook (larger id yields in mutual pairs) + record MST edge
        for (int c = tid; c < nmin; c += 1024) {
            uint32_t s = sel[c];
            if (s == 0xFFFFFFFFu) continue;
            uint32_t d = s & 0xFFFFu;
            uint32_t sd = sel[d];
            bool mutual = ((sd & 0xFFFFu) == (uint32_t)c);
            if (mutual && (uint32_t)c < d) continue;    // smaller stays root
            par[c] = (uint16_t)d;
            int pos = atomicAdd(&g_mcnt[img], 1);
            mst[pos] = ((unsigned long long)(s >> 16) << 32)
                     | ((unsigned long long)c << 16) | (unsigned long long)d;
            s_hooks = 1;
        }
        __syncthreads();
        if (s_hooks == 0) break;

        // full flatten: 16 pointer-doubling sweeps cover any depth <= 65536
        for (int it = 0; it < 16; it++) {
            for (int i = tid; i < nmin; i += 1024) par[i] = par[par[i]];
            __syncthreads();
        }

        // relabel edge endpoints with root ids
        for (int i = tid; i < m; i += 1024) {
            unsigned long long e = ed[i];
            uint32_t lo = (uint32_t)e;
            uint32_t cu = lo >> 16, cv = lo & 0xFFFFu;
            if (cu == cv) continue;
            cu = par[cu]; cv = par[cv];
            ed[i] = (e & 0xFFFFFFFF00000000ull)
                  | ((unsigned long long)cu << 16) | (unsigned long long)cv;
        }
        __syncthreads();
    }
}

// ---------------- 9) radix sort MST edges by death rank (bits [32,48)) ------
__global__ void __launch_bounds__(1024, 1) k_mstsort() {
    extern __shared__ uint32_t hist[];          // 64 KB
    __shared__ uint32_t warpsum[32];
    const int img  = blockIdx.x;
    const int tid  = threadIdx.x;
    const int lane = tid & 31;
    const int wid  = tid >> 5;
    const int n = g_mcnt[img];
    const size_t off = (size_t)img * PMAX;

    for (int pass = 0; pass < 4; pass++) {
        const unsigned long long* src = (pass & 1) ? g_mstB + off : g_mstA + off;
        unsigned long long*       dst = (pass & 1) ? g_mstA + off : g_mstB + off;
        const int shift = 32 + pass * 4;

        #pragma unroll
        for (int i = 0; i < 16; i++) hist[i * 1024 + tid] = 0;
        __syncthreads();

        const int base = tid * 32;
        for (int j = 0; j < 32; j++) {
            int idx = base + j;
            if (idx < n) {
                uint32_t d = (uint32_t)(src[idx] >> shift) & 15u;
                hist[(d << 10) + tid]++;
            }
        }
        __syncthreads();

        const int sb = tid * 16;
        uint32_t sum = 0;
        #pragma unroll
        for (int i = 0; i < 16; i++) sum += hist[sb + i];
        uint32_t v = sum;
        #pragma unroll
        for (int o = 1; o < 32; o <<= 1) {
            uint32_t t = __shfl_up_sync(0xFFFFFFFFu, v, o);
            if (lane >= o) v += t;
        }
        if (lane == 31) warpsum[wid] = v;
        __syncthreads();
        if (wid == 0) {
            uint32_t w  = warpsum[lane];
            uint32_t wv = w;
            #pragma unroll
            for (int o = 1; o < 32; o <<= 1) {
                uint32_t t = __shfl_up_sync(0xFFFFFFFFu, wv, o);
                if (lane >= o) wv += t;
            }
            warpsum[lane] = wv - w;
        }
        __syncthreads();
        uint32_t run = (v - sum) + warpsum[wid];
        #pragma unroll
        for (int i = 0; i < 16; i++) { uint32_t t = hist[sb + i]; hist[sb + i] = run; run += t; }
        __syncthreads();

        for (int j = 0; j < 32; j++) {
            int idx = base + j;
            if (idx < n) {
                unsigned long long k = src[idx];
                uint32_t d = (uint32_t)(k >> shift) & 15u;
                dst[hist[(d << 10) + tid]++] = k;
            }
        }
        __syncthreads();
    }
}

// ---------------- 10) serial pairing over sorted MST edges ------------------
__device__ __forceinline__ uint32_t uf_find(uint16_t* par, uint32_t x) {
    uint32_t p = par[x];
    while (p != x) {                 // path halving
        uint32_t g = par[p];
        par[x] = (uint16_t)g;
        x = g;
        p = par[x];
    }
    return x;
}

__global__ void __launch_bounds__(1024, 1) k_pair() {
    extern __shared__ uint16_t par[];            // 64 KB
    const int img = blockIdx.x;
    const int tid = threadIdx.x;
    const int nmin = g_nmin[img];
    for (int i = tid; i < nmin; i += 1024) par[i] = (uint16_t)i;
    __syncthreads();
    if (tid != 0) return;

    const unsigned long long* __restrict__ mst = g_mstA + (size_t)img * PMAX;
    uint32_t* __restrict__ out = g_pairs + (size_t)img * PMAX;
    const int m = g_mcnt[img];

    int pc = 0;
    for (int i = 0; i < m; i++) {
        unsigned long long e = mst[i];
        uint32_t cu = ((uint32_t)e) >> 16, cv = (uint32_t)e & 0xFFFFu;
        uint32_t ru = uf_find(par, cu);
        uint32_t rv = uf_find(par, cv);
        if (ru == rv) continue;                  // defensive; MST has no cycles
        uint32_t die  = ru > rv ? ru : rv;       // younger = larger dense id
        uint32_t keep = ru > rv ? rv : ru;
        par[die] = (uint16_t)keep;
        out[pc++] = (((uint32_t)(e >> 32)) << 16) | die;   // death rank | dying id
    }
    g_pcnt[img] = pc;
}

// ---------------- 11) parallel top-5 lifetimes + per-image loss -------------
__device__ __forceinline__ void top5_ins(float& t0, float& t1, float& t2,
                                         float& t3, float& t4, float life) {
    if (life <= t4) return;
    if (life > t0)      { t4 = t3; t3 = t2; t2 = t1; t1 = t0; t0 = life; }
    else if (life > t1) { t4 = t3; t3 = t2; t2 = t1; t1 = life; }
    else if (life > t2) { t4 = t3; t3 = t2; t2 = life; }
    else if (life > t3) { t4 = t3; t3 = life; }
    else                  t4 = life;
}

__global__ void __launch_bounds__(1024, 1) k_top() {
    __shared__ float cand[1024 * 5];
    const int img = blockIdx.x;
    const int tid = threadIdx.x;
    const uint32_t* __restrict__ pr = g_pairs + (size_t)img * PMAX;
    const uint16_t* __restrict__ mr = g_minrank + (size_t)img * PMAX;
    const float* __restrict__ sf = g_sortedf + ((size_t)img << 16);
    const int m = g_pcnt[img];

    float t0 = -1e30f, t1 = -1e30f, t2 = -1e30f, t3 = -1e30f, t4 = -1e30f;
    for (int i = tid; i < m; i += 1024) {
        uint32_t e = pr[i];
        float life = sf[e >> 16] - sf[mr[e & 0xFFFFu]];
        top5_ins(t0, t1, t2, t3, t4, life);
    }
    cand[tid * 5 + 0] = t0; cand[tid * 5 + 1] = t1; cand[tid * 5 + 2] = t2;
    cand[tid * 5 + 3] = t3; cand[tid * 5 + 4] = t4;
    __syncthreads();
    if (tid == 0) {
        float s0 = -1e30f, s1 = -1e30f, s2 = -1e30f, s3 = -1e30f, s4 = -1e30f;
        for (int i = 0; i < 1024 * 5; i++) top5_ins(s0, s1, s2, s3, s4, cand[i]);
        if (s0 < -1e29f) s0 = 0.0f;
        if (s1 < -1e29f) s1 = 0.0f;
        if (s2 < -1e29f) s2 = 0.0f;
        if (s3 < -1e29f) s3 = 0.0f;
        if (s4 < -1e29f) s4 = 0.0f;
        float d0 = s0 - 0.5f, d1 = s1 - 0.5f, d2 = s2 - 0.5f, d3 = s3 - 0.5f, d4 = s4 - 0.5f;
        g_loss[img] = (d0 * d0 + d1 * d1 + d2 * d2 + d3 * d3 + d4 * d4) * 0.2f;
    }
}

__global__ void k_final(float* out) {
    out[0] = (g_loss[0] + g_loss[1] + g_loss[2] + g_loss[3]) * 25.0f; // mean/4 * 100
}

// ---------------- launch -----------------------------------------------------
extern "C" void kernel_launch(void* const* d_in, const int* in_sizes, int n_in,
                              void* d_out, int out_size) {
    (void)in_sizes; (void)n_in; (void)out_size;
    const float* prob = (const float*)d_in[0];
    const float* roi  = (const float*)d_in[1];
    float* out = (float*)d_out;

    cudaFuncSetAttribute(k_radix,   cudaFuncAttributeMaxDynamicSharedMemorySize, 64 * 1024);
    cudaFuncSetAttribute(k_mstsort, cudaFuncAttributeMaxDynamicSharedMemorySize, 64 * 1024);
    cudaFuncSetAttribute(k_basin,   cudaFuncAttributeMaxDynamicSharedMemorySize, NPIX * 2);
    cudaFuncSetAttribute(k_boruvka, cudaFuncAttributeMaxDynamicSharedMemorySize, 192 * 1024);
    cudaFuncSetAttribute(k_pair,    cudaFuncAttributeMaxDynamicSharedMemorySize, 64 * 1024);

    const int nTot = NIMG * NPIX;
    k_init<<<(nTot + 255) / 256, 256>>>(prob, roi);
    k_radix<<<NIMG, 1024, 64 * 1024>>>();
    k_rank<<<(nTot + 255) / 256, 256>>>();
    k_nbr<<<(nTot + 255) / 256, 256>>>();
    k_basin<<<NIMG, 1024, NPIX * 2>>>();
    k_dense<<<NIMG, 1024>>>();
    k_edges<<<(nTot + 255) / 256, 256>>>();
    k_boruvka<<<NIMG, 1024, 192 * 1024>>>();
    k_mstsort<<<NIMG, 1024, 64 * 1024>>>();
    k_pair<<<NIMG, 1024, 64 * 1024>>>();
    k_top<<<NIMG, 1024>>>();
    k_final<<<1, 1>>>(out);
}

// round 6
// speedup vs baseline: 4.6412x; 1.0027x over previous
#include <cuda_runtime.h>
#include <stdint.h>

#define NPIX 65536
#define NIMG 4
#define EMAX 131072            // >= 2*256*255 edges per image
#define PMAX 32768             // max #local minima (independent set bound)

// ---------------- device scratch (no allocations allowed) ----------------
__device__ uint32_t g_keyA[NIMG * NPIX];
__device__ uint32_t g_keyB[NIMG * NPIX];
__device__ uint32_t g_payA[NIMG * NPIX];
__device__ uint32_t g_payB[NIMG * NPIX];
__device__ float    g_fval[NIMG * NPIX];
__device__ uint16_t g_rank16[NIMG * NPIX];
__device__ float    g_sortedf[NIMG * NPIX];
__device__ unsigned long long g_nbrs[NIMG * NPIX];
__device__ uint16_t g_basin[NIMG * NPIX];
__device__ uint16_t g_dense[NIMG * NPIX];
__device__ uint16_t g_minrank[NIMG * PMAX];
__device__ int      g_nmin[NIMG];
__device__ unsigned long long g_edges[NIMG * EMAX];
__device__ int      g_ecnt[NIMG];
__device__ unsigned long long g_mstA[NIMG * PMAX];
__device__ unsigned long long g_mstB[NIMG * PMAX];
__device__ int      g_mcnt[NIMG];
__device__ uint32_t g_pairs[NIMG * PMAX];
__device__ int      g_pcnt[NIMG];
__device__ float    g_loss[NIMG];

// ---------------- 1) f = 1 - prob*roi, keys = float bits --------------------
__global__ void k_init(const float* __restrict__ prob, const float* __restrict__ roi) {
    int i = blockIdx.x * blockDim.x + threadIdx.x;
    if (i < NIMG) { g_ecnt[i] = 0; g_mcnt[i] = 0; }
    if (i < NIMG * NPIX) {
        float f = 1.0f - prob[i] * roi[i];
        g_fval[i] = f;
        g_keyA[i] = __float_as_uint(f);   // f>0 -> bit order == float order
        g_payA[i] = (uint32_t)(i & (NPIX - 1));
    }
}

// ---------------- 2) per-image stable LSD radix sort (8 x 4-bit) ------------
__global__ void __launch_bounds__(1024, 1) k_radix() {
    extern __shared__ uint32_t hist[];          // 64 KB
    __shared__ uint32_t warpsum[32];
    const int img  = blockIdx.x;
    const int tid  = threadIdx.x;
    const int lane = tid & 31;
    const int wid  = tid >> 5;
    const uint32_t off = (uint32_t)img * NPIX;

    for (int pass = 0; pass < 8; pass++) {
        uint32_t *src, *dst, *ps, *pd;
        if (pass & 1) { src = g_keyB; dst = g_keyA; ps = g_payB; pd = g_payA; }
        else          { src = g_keyA; dst = g_keyB; ps = g_payA; pd = g_payB; }
        src += off; dst += off; ps += off; pd += off;
        const int shift = pass * 4;

        #pragma unroll
        for (int i = 0; i < 16; i++) hist[i * 1024 + tid] = 0;
        __syncthreads();

        const int base = tid * 64;
        for (int j = 0; j < 64; j++) {
            uint32_t d = (src[base + j] >> shift) & 15u;
            hist[(d << 10) + tid]++;
        }
        __syncthreads();

        const int sb = tid * 16;
        uint32_t sum = 0;
        #pragma unroll
        for (int i = 0; i < 16; i++) sum += hist[sb + i];
        uint32_t v = sum;
        #pragma unroll
        for (int o = 1; o < 32; o <<= 1) {
            uint32_t n = __shfl_up_sync(0xFFFFFFFFu, v, o);
            if (lane >= o) v += n;
        }
        if (lane == 31) warpsum[wid] = v;
        __syncthreads();
        if (wid == 0) {
            uint32_t w  = warpsum[lane];
            uint32_t wv = w;
            #pragma unroll
            for (int o = 1; o < 32; o <<= 1) {
                uint32_t n = __shfl_up_sync(0xFFFFFFFFu, wv, o);
                if (lane >= o) wv += n;
            }
            warpsum[lane] = wv - w;
        }
        __syncthreads();
        uint32_t run = (v - sum) + warpsum[wid];
        #pragma unroll
        for (int i = 0; i < 16; i++) { uint32_t t = hist[sb + i]; hist[sb + i] = run; run += t; }
        __syncthreads();

        for (int j = 0; j < 64; j++) {
            uint32_t k = src[base + j];
            uint32_t d = (k >> shift) & 15u;
            uint32_t pos = hist[(d << 10) + tid]++;
            dst[pos] = k;
            pd[pos]  = ps[base + j];
        }
        __syncthreads();
    }
}

// ---------------- 3) rank (inverse perm) + f gathered in rank order ---------
__global__ void k_rank() {
    int i = blockIdx.x * blockDim.x + threadIdx.x;
    if (i < NIMG * NPIX) {
        int img = i >> 16;
        uint32_t pix = g_payA[i];
        g_rank16[(img << 16) + pix] = (uint16_t)(i & (NPIX - 1));
        g_sortedf[i] = g_fval[(img << 16) + pix];
    }
}

// ---------------- 4) packed neighbor ranks, indexed by rank -----------------
__global__ void k_nbr() {
    int i = blockIdx.x * blockDim.x + threadIdx.x;
    if (i < NIMG * NPIX) {
        int img = i >> 16;
        uint32_t pix = (uint32_t)(i & (NPIX - 1));
        const uint16_t* rk = g_rank16 + ((size_t)img << 16);
        uint32_t r = rk[pix];
        int y = pix >> 8, x = pix & 255;
        unsigned long long n0 = (y > 0)   ? (unsigned long long)rk[pix - 256] : 0xFFFFull;
        unsigned long long n1 = (y < 255) ? (unsigned long long)rk[pix + 256] : 0xFFFFull;
        unsigned long long n2 = (x > 0)   ? (unsigned long long)rk[pix - 1]   : 0xFFFFull;
        unsigned long long n3 = (x < 255) ? (unsigned long long)rk[pix + 1]   : 0xFFFFull;
        g_nbrs[((size_t)img << 16) + r] = n0 | (n1 << 16) | (n2 << 32) | (n3 << 48);
    }
}

// ---------------- 5) basins: steepest-descent forest + pointer doubling -----
__global__ void __launch_bounds__(1024, 1) k_basin() {
    extern __shared__ uint16_t bs[];             // 128 KB
    const int img = blockIdx.x;
    const int tid = threadIdx.x;
    const unsigned long long* __restrict__ nb = g_nbrs + ((size_t)img << 16);

    for (int i = tid; i < NPIX; i += 1024) {
        unsigned long long w = nb[i];
        uint32_t m0 = (uint32_t)(w & 0xFFFF), m1 = (uint32_t)((w >> 16) & 0xFFFF);
        uint32_t m2 = (uint32_t)((w >> 32) & 0xFFFF), m3 = (uint32_t)(w >> 48);
        uint32_t m = min(min(m0, m1), min(m2, m3));
        bs[i] = (uint16_t)((m < (uint32_t)i) ? m : (uint32_t)i);
    }
    __syncthreads();
    for (int round = 0; round < 16; round++) {
        for (int i = tid; i < NPIX; i += 1024) {
            uint32_t p = bs[i];
            bs[i] = bs[p];
        }
        __syncthreads();
    }
    uint16_t* out = g_basin + ((size_t)img << 16);
    for (int i = tid; i < NPIX; i += 1024) out[i] = bs[i];
}

// ---------------- 6) dense basin ids (ascending rank => ascending birth) ----
__global__ void __launch_bounds__(1024, 1) k_dense() {
    __shared__ uint32_t warpsum[32];
    const int img = blockIdx.x, tid = threadIdx.x;
    const int lane = tid & 31, wid = tid >> 5;
    const uint16_t* bs = g_basin + ((size_t)img << 16);
    const int base = tid * 64;

    uint32_t cnt = 0;
    for (int j = 0; j < 64; j++) cnt += (bs[base + j] == (uint16_t)(base + j));
    uint32_t v = cnt;
    #pragma unroll
    for (int o = 1; o < 32; o <<= 1) {
        uint32_t n = __shfl_up_sync(0xFFFFFFFFu, v, o);
        if (lane >= o) v += n;
    }
    if (lane == 31) warpsum[wid] = v;
    __syncthreads();
    if (wid == 0) {
        uint32_t w  = warpsum[lane];
        uint32_t wv = w;
        #pragma unroll
        for (int o = 1; o < 32; o <<= 1) {
            uint32_t n = __shfl_up_sync(0xFFFFFFFFu, wv, o);
            if (lane >= o) wv += n;
        }
        warpsum[lane] = wv - w;
    }
    __syncthreads();
    uint32_t run = (v - cnt) + warpsum[wid];
    uint16_t* dn = g_dense   + ((size_t)img << 16);
    uint16_t* mr = g_minrank + (size_t)img * PMAX;
    for (int j = 0; j < 64; j++) {
        int i = base + j;
        if (bs[i] == (uint16_t)i) { dn[i] = (uint16_t)run; mr[run] = (uint16_t)i; run++; }
    }
    if (tid == 1023) g_nmin[img] = (int)run;
}

// ---------------- 7) emit crossing edges as (w | cu_dense | cv_dense) -------
__global__ void k_edges() {
    int i = blockIdx.x * blockDim.x + threadIdx.x;
    if (i >= NIMG * NPIX) return;
    int img = i >> 16;
    uint32_t r = (uint32_t)(i & (NPIX - 1));
    const uint16_t* bs = g_basin + ((size_t)img << 16);
    const uint16_t* dn = g_dense + ((size_t)img << 16);
    unsigned long long w = g_nbrs[i];
    uint32_t br = bs[r];

    unsigned long long recs[3];
    int cnt = 0;
    #pragma unroll
    for (int k = 0; k < 4; k++) {
        uint32_t q = (uint32_t)(w >> (k * 16)) & 0xFFFFu;
        if (q < r) {
            uint32_t bq = bs[q];
            if (bq != br)
                recs[cnt++] = ((unsigned long long)r << 32)
                            | ((unsigned long long)dn[br] << 16)
                            | (unsigned long long)dn[bq];
        }
    }
    int lane = threadIdx.x & 31;
    int pre = cnt;
    #pragma unroll
    for (int o = 1; o < 32; o <<= 1) {
        int n = __shfl_up_sync(0xFFFFFFFFu, pre, o);
        if (lane >= o) pre += n;
    }
    int total = __shfl_sync(0xFFFFFFFFu, pre, 31);
    int excl = pre - cnt;
    int base = 0;
    if (lane == 31 && total > 0) base = atomicAdd(&g_ecnt[img], total);
    base = __shfl_sync(0xFFFFFFFFu, base, 31);
    unsigned long long* er = g_edges + (size_t)img * EMAX;
    for (int j = 0; j < cnt; j++) er[base + excl + j] = recs[j];
}

// ---------------- 8) parallel Boruvka MST on the basin graph ----------------
// sel key = (w<<16)|other: a cycle of hooks forces equal w and contradictory
// id orderings except mutual 2-cycles, which the "larger id hooks" rule breaks.
// Mutual selections provably share the same w, so either edge is MST-valid.
__global__ void __launch_bounds__(1024, 1) k_boruvka() {
    extern __shared__ char smraw[];
    uint16_t* par = (uint16_t*)smraw;              // 64 KB (32768 u16)
    uint32_t* sel = (uint32_t*)(smraw + 65536);    // 128 KB (32768 u32)
    __shared__ int s_hooks;
    const int img = blockIdx.x, tid = threadIdx.x;
    const int nmin = g_nmin[img];
    const int m = g_ecnt[img];
    unsigned long long* ed  = g_edges + (size_t)img * EMAX;
    unsigned long long* mst = g_mstA  + (size_t)img * PMAX;

    for (int i = tid; i < nmin; i += 1024) par[i] = (uint16_t)i;

    for (int round = 0; round < 17; round++) {
        if (tid == 0) s_hooks = 0;
        for (int i = tid; i < nmin; i += 1024) sel[i] = 0xFFFFFFFFu;
        __syncthreads();

        // select lightest incident edge per component
        for (int i = tid; i < m; i += 1024) {
            unsigned long long e = ed[i];
            uint32_t lo = (uint32_t)e;
            uint32_t cu = lo >> 16, cv = lo & 0xFFFFu;
            if (cu == cv) continue;
            uint32_t w = (uint32_t)(e >> 32);
            atomicMin(&sel[cu], (w << 16) | cv);
            atomicMin(&sel[cv], (w << 16) | cu);
        }
        __syncthreads();

        // hook (larger id yields in mutual pairs) + record MST edge
        for (int c = tid; c < nmin; c += 1024) {
            uint32_t s = sel[c];
            if (s == 0xFFFFFFFFu) continue;
            uint32_t d = s & 0xFFFFu;
            uint32_t sd = sel[d];
            bool mutual = ((sd & 0xFFFFu) == (uint32_t)c);
            if (mutual && (uint32_t)c < d) continue;    // smaller stays root
            par[c] = (uint16_t)d;
            int pos = atomicAdd(&g_mcnt[img], 1);
            mst[pos] = ((unsigned long long)(s >> 16) << 32)
                     | ((unsigned long long)c << 16) | (unsigned long long)d;
            s_hooks = 1;
        }
        __syncthreads();
        if (s_hooks == 0) break;

        // full flatten: 16 pointer-doubling sweeps cover any depth <= 65536
        for (int it = 0; it < 16; it++) {
            for (int i = tid; i < nmin; i += 1024) par[i] = par[par[i]];
            __syncthreads();
        }

        // relabel edge endpoints with root ids
        for (int i = tid; i < m; i += 1024) {
            unsigned long long e = ed[i];
            uint32_t lo = (uint32_t)e;
            uint32_t cu = lo >> 16, cv = lo & 0xFFFFu;
            if (cu == cv) continue;
            cu = par[cu]; cv = par[cv];
            ed[i] = (e & 0xFFFFFFFF00000000ull)
                  | ((unsigned long long)cu << 16) | (unsigned long long)cv;
        }
        __syncthreads();
    }
}

// ---------------- 9) radix sort MST edges by death rank (bits [32,48)) ------
__global__ void __launch_bounds__(1024, 1) k_mstsort() {
    extern __shared__ uint32_t hist[];          // 64 KB
    __shared__ uint32_t warpsum[32];
    const int img  = blockIdx.x;
    const int tid  = threadIdx.x;
    const int lane = tid & 31;
    const int wid  = tid >> 5;
    const int n = g_mcnt[img];
    const size_t off = (size_t)img * PMAX;

    for (int pass = 0; pass < 4; pass++) {
        const unsigned long long* src = (pass & 1) ? g_mstB + off : g_mstA + off;
        unsigned long long*       dst = (pass & 1) ? g_mstA + off : g_mstB + off;
        const int shift = 32 + pass * 4;

        #pragma unroll
        for (int i = 0; i < 16; i++) hist[i * 1024 + tid] = 0;
        __syncthreads();

        const int base = tid * 32;
        for (int j = 0; j < 32; j++) {
            int idx = base + j;
            if (idx < n) {
                uint32_t d = (uint32_t)(src[idx] >> shift) & 15u;
                hist[(d << 10) + tid]++;
            }
        }
        __syncthreads();

        const int sb = tid * 16;
        uint32_t sum = 0;
        #pragma unroll
        for (int i = 0; i < 16; i++) sum += hist[sb + i];
        uint32_t v = sum;
        #pragma unroll
        for (int o = 1; o < 32; o <<= 1) {
            uint32_t t = __shfl_up_sync(0xFFFFFFFFu, v, o);
            if (lane >= o) v += t;
        }
        if (lane == 31) warpsum[wid] = v;
        __syncthreads();
        if (wid == 0) {
            uint32_t w  = warpsum[lane];
            uint32_t wv = w;
            #pragma unroll
            for (int o = 1; o < 32; o <<= 1) {
                uint32_t t = __shfl_up_sync(0xFFFFFFFFu, wv, o);
                if (lane >= o) wv += t;
            }
            warpsum[lane] = wv - w;
        }
        __syncthreads();
        uint32_t run = (v - sum) + warpsum[wid];
        #pragma unroll
        for (int i = 0; i < 16; i++) { uint32_t t = hist[sb + i]; hist[sb + i] = run; run += t; }
        __syncthreads();

        for (int j = 0; j < 32; j++) {
            int idx = base + j;
            if (idx < n) {
                unsigned long long k = src[idx];
                uint32_t d = (uint32_t)(k >> shift) & 15u;
                dst[hist[(d << 10) + tid]++] = k;
            }
        }
        __syncthreads();
    }
}

// ---------------- 10) serial pairing over sorted MST edges ------------------
__device__ __forceinline__ uint32_t uf_find(uint16_t* par, uint32_t x) {
    uint32_t p = par[x];
    while (p != x) {                 // path halving
        uint32_t g = par[p];
        par[x] = (uint16_t)g;
        x = g;
        p = par[x];
    }
    return x;
}

__global__ void __launch_bounds__(1024, 1) k_pair() {
    extern __shared__ uint16_t par[];            // 64 KB
    const int img = blockIdx.x;
    const int tid = threadIdx.x;
    const int nmin = g_nmin[img];
    for (int i = tid; i < nmin; i += 1024) par[i] = (uint16_t)i;
    __syncthreads();
    if (tid != 0) return;

    const unsigned long long* __restrict__ mst = g_mstA + (size_t)img * PMAX;
    uint32_t* __restrict__ out = g_pairs + (size_t)img * PMAX;
    const int m = g_mcnt[img];

    int pc = 0;
    for (int i = 0; i < m; i++) {
        unsigned long long e = mst[i];
        uint32_t cu = ((uint32_t)e) >> 16, cv = (uint32_t)e & 0xFFFFu;
        uint32_t ru = uf_find(par, cu);
        uint32_t rv = uf_find(par, cv);
        if (ru == rv) continue;                  // defensive; MST has no cycles
        uint32_t die  = ru > rv ? ru : rv;       // younger = larger dense id
        uint32_t keep = ru > rv ? rv : ru;
        par[die] = (uint16_t)keep;
        out[pc++] = (((uint32_t)(e >> 32)) << 16) | die;   // death rank | dying id
    }
    g_pcnt[img] = pc;
}

// ---------------- 11) parallel top-5 lifetimes + per-image loss -------------
__device__ __forceinline__ void top5_ins(float& t0, float& t1, float& t2,
                                         float& t3, float& t4, float life) {
    if (life <= t4) return;
    if (life > t0)      { t4 = t3; t3 = t2; t2 = t1; t1 = t0; t0 = life; }
    else if (life > t1) { t4 = t3; t3 = t2; t2 = t1; t1 = life; }
    else if (life > t2) { t4 = t3; t3 = t2; t2 = life; }
    else if (life > t3) { t4 = t3; t3 = life; }
    else                  t4 = life;
}

__global__ void __launch_bounds__(1024, 1) k_top() {
    __shared__ float cand[1024 * 5];
    const int img = blockIdx.x;
    const int tid = threadIdx.x;
    const uint32_t* __restrict__ pr = g_pairs + (size_t)img * PMAX;
    const uint16_t* __restrict__ mr = g_minrank + (size_t)img * PMAX;
    const float* __restrict__ sf = g_sortedf + ((size_t)img << 16);
    const int m = g_pcnt[img];

    float t0 = -1e30f, t1 = -1e30f, t2 = -1e30f, t3 = -1e30f, t4 = -1e30f;
    for (int i = tid; i < m; i += 1024) {
        uint32_t e = pr[i];
        float life = sf[e >> 16] - sf[mr[e & 0xFFFFu]];
        top5_ins(t0, t1, t2, t3, t4, life);
    }
    cand[tid * 5 + 0] = t0; cand[tid * 5 + 1] = t1; cand[tid * 5 + 2] = t2;
    cand[tid * 5 + 3] = t3; cand[tid * 5 + 4] = t4;
    __syncthreads();
    if (tid == 0) {
        float s0 = -1e30f, s1 = -1e30f, s2 = -1e30f, s3 = -1e30f, s4 = -1e30f;
        for (int i = 0; i < 1024 * 5; i++) top5_ins(s0, s1, s2, s3, s4, cand[i]);
        if (s0 < -1e29f) s0 = 0.0f;
        if (s1 < -1e29f) s1 = 0.0f;
        if (s2 < -1e29f) s2 = 0.0f;
        if (s3 < -1e29f) s3 = 0.0f;
        if (s4 < -1e29f) s4 = 0.0f;
        float d0 = s0 - 0.5f, d1 = s1 - 0.5f, d2 = s2 - 0.5f, d3 = s3 - 0.5f, d4 = s4 - 0.5f;
        g_loss[img] = (d0 * d0 + d1 * d1 + d2 * d2 + d3 * d3 + d4 * d4) * 0.2f;
    }
}

__global__ void k_final(float* out) {
    out[0] = (g_loss[0] + g_loss[1] + g_loss[2] + g_loss[3]) * 25.0f; // mean/4 * 100
}

// ---------------- launch -----------------------------------------------------
extern "C" void kernel_launch(void* const* d_in, const int* in_sizes, int n_in,
                              void* d_out, int out_size) {
    (void)in_sizes; (void)n_in; (void)out_size;
    const float* prob = (const float*)d_in[0];
    const float* roi  = (const float*)d_in[1];
    float* out = (float*)d_out;

    cudaFuncSetAttribute(k_radix,   cudaFuncAttributeMaxDynamicSharedMemorySize, 64 * 1024);
    cudaFuncSetAttribute(k_mstsort, cudaFuncAttributeMaxDynamicSharedMemorySize, 64 * 1024);
    cudaFuncSetAttribute(k_basin,   cudaFuncAttributeMaxDynamicSharedMemorySize, NPIX * 2);
    cudaFuncSetAttribute(k_boruvka, cudaFuncAttributeMaxDynamicSharedMemorySize, 192 * 1024);
    cudaFuncSetAttribute(k_pair,    cudaFuncAttributeMaxDynamicSharedMemorySize, 64 * 1024);

    const int nTot = NIMG * NPIX;
    k_init<<<(nTot + 255) / 256, 256>>>(prob, roi);
    k_radix<<<NIMG, 1024, 64 * 1024>>>();
    k_rank<<<(nTot + 255) / 256, 256>>>();
    k_nbr<<<(nTot + 255) / 256, 256>>>();
    k_basin<<<NIMG, 1024, NPIX * 2>>>();
    k_dense<<<NIMG, 1024>>>();
    k_edges<<<(nTot + 255) / 256, 256>>>();
    k_boruvka<<<NIMG, 1024, 192 * 1024>>>();
    k_mstsort<<<NIMG, 1024, 64 * 1024>>>();
    k_pair<<<NIMG, 1024, 64 * 1024>>>();
    k_top<<<NIMG, 1024>>>();
    k_final<<<1, 1>>>(out);
}